// round 1
// baseline (speedup 1.0000x reference)
#include <cuda_runtime.h>
#include <math.h>

#define T    2048
#define H    2048
#define NH   16
#define NKV  4
#define HD   128
#define E    8
#define I_DIM 4096
#define QKVW ((NH + 2*NKV) * HD)   /* 3072 */
#define EPSN 1e-5f
#define THETA_F 500000.0f
#define ATTN_SCALE 0.08838834764831845f  /* 128^-0.5 */

/* ------------------------- scratch (device globals) ------------------------- */
__device__ float g_res [T*H];
__device__ float g_x   [T*H];      /* x (ln1 out), later reused for x2 */
__device__ float g_qkv [T*QKVW];
__device__ float g_attn[T*H];
__device__ float g_xw  [T*H];
__device__ float g_gbuf[(size_t)T*I_DIM];
__device__ float g_ubuf[(size_t)T*I_DIM];
__device__ int   g_topidx[T];
__device__ int   g_perm[T];
__device__ int   g_cnt[E];
__device__ int   g_off[E];

/* ------------------------- add + rmsnorm ------------------------- */
/* xout = rmsnorm(a (+b), w); optionally store a+b into res */
__global__ void addnorm_kernel(const float* __restrict__ a, const float* __restrict__ b,
                               const float* __restrict__ w, float* __restrict__ res,
                               float* __restrict__ xout)
{
    int t = blockIdx.x;
    int tid = threadIdx.x;
    const int PER = H / 256;
    size_t base = (size_t)t * H;
    float v[PER];
    float ss = 0.f;
#pragma unroll
    for (int u = 0; u < PER; u++) {
        int c = tid + u * 256;
        float val = a[base + c];
        if (b) val += b[base + c];
        v[u] = val;
        if (res) res[base + c] = val;
        ss += val * val;
    }
    __shared__ float red[256];
    red[tid] = ss;
    __syncthreads();
    for (int s = 128; s > 0; s >>= 1) {
        if (tid < s) red[tid] += red[tid + s];
        __syncthreads();
    }
    float scale = rsqrtf(red[0] / (float)H + EPSN);
#pragma unroll
    for (int u = 0; u < PER; u++) {
        int c = tid + u * 256;
        xout[base + c] = v[u] * scale * w[c];
    }
}

/* ------------------------- rope + q/k rmsnorm (in-place on qkv) ------------------------- */
__global__ void rope_qknorm_kernel(float* __restrict__ qkv, const int* __restrict__ positions)
{
    int t  = blockIdx.x;
    int hh = blockIdx.y;                  /* 0..NH+NKV-1 : q heads then k heads */
    int col0 = (hh < NH) ? hh * HD : (NH * HD + (hh - NH) * HD);
    float* p = qkv + (size_t)t * QKVW + col0;
    int d = threadIdx.x;                  /* 0..127 */
    float pos = (float)positions[t];
    int i = (d < 64) ? d : d - 64;
    float invf = powf(THETA_F, -(float)i / 64.f);
    float ang = pos * invf;
    float c = cosf(ang), s = sinf(ang);
    float x1 = p[i], x2 = p[i + 64];
    float val = (d < 64) ? (x1 * c - x2 * s) : (x2 * c + x1 * s);

    __shared__ float red[128];
    red[d] = val * val;
    __syncthreads();
    for (int st = 64; st > 0; st >>= 1) {
        if (d < st) red[d] += red[d + st];
        __syncthreads();
    }
    float scale = rsqrtf(red[0] / (float)HD + EPSN);
    p[d] = val * scale;   /* all cross-element reads completed before barriers above */
}

/* ------------------------- flash attention (causal, GQA) ------------------------- */
__global__ void attn_kernel(const float* __restrict__ qkv, float* __restrict__ out)
{
    int qb = blockIdx.x;                /* 32-query tile */
    int h  = blockIdx.y;                /* q head */
    int tid = threadIdx.x;              /* 128 threads */
    int r = tid >> 2;                   /* query row within tile 0..31 */
    int j = tid & 3;                    /* 32-dim slice 0..3 */
    int qt = qb * 32 + r;
    int kvh = h >> 2;                   /* GQA: rep=4 */

    const float* qptr = qkv + (size_t)qt * QKVW + h * HD + j * 32;
    float qreg[32];
#pragma unroll
    for (int d = 0; d < 32; d++) qreg[d] = qptr[d];

    __shared__ float Ks[32][128];
    __shared__ float Vs[32][128];

    float m = -1e30f, l = 0.f;
    float acc[32];
#pragma unroll
    for (int d = 0; d < 32; d++) acc[d] = 0.f;

    for (int kt = 0; kt <= qb; kt++) {
        for (int li = tid; li < 32 * 128; li += 128) {
            int row = li >> 7, col = li & 127;
            size_t gb = (size_t)(kt * 32 + row) * QKVW + kvh * HD + col;
            Ks[row][col] = qkv[gb + NH * HD];
            Vs[row][col] = qkv[gb + (NH + NKV) * HD];
        }
        __syncthreads();

        float sc[32];
#pragma unroll 4
        for (int c = 0; c < 32; c++) {
            float a4 = 0.f;
#pragma unroll
            for (int d = 0; d < 32; d++) a4 = fmaf(qreg[d], Ks[c][j * 32 + d], a4);
            sc[c] = a4;
        }
#pragma unroll
        for (int c = 0; c < 32; c++) {
            sc[c] += __shfl_xor_sync(0xffffffffu, sc[c], 1);
            sc[c] += __shfl_xor_sync(0xffffffffu, sc[c], 2);
            int ka = kt * 32 + c;
            sc[c] = (ka <= qt) ? sc[c] * ATTN_SCALE : -1e30f;
        }
        float mt = -1e30f;
#pragma unroll
        for (int c = 0; c < 32; c++) mt = fmaxf(mt, sc[c]);
        float mnew = fmaxf(m, mt);
        float alpha = __expf(m - mnew);
        float psum = 0.f;
#pragma unroll
        for (int c = 0; c < 32; c++) { sc[c] = __expf(sc[c] - mnew); psum += sc[c]; }
        l = l * alpha + psum;
        m = mnew;
#pragma unroll
        for (int d = 0; d < 32; d++) acc[d] *= alpha;
#pragma unroll 4
        for (int c = 0; c < 32; c++) {
            float pc = sc[c];
#pragma unroll
            for (int d = 0; d < 32; d++) acc[d] = fmaf(pc, Vs[c][j * 32 + d], acc[d]);
        }
        __syncthreads();
    }
    float inv = 1.f / l;
    float* op = out + (size_t)qt * H + h * HD + j * 32;
#pragma unroll
    for (int d = 0; d < 32; d++) op[d] = acc[d] * inv;
}

/* ------------------------- SGEMM core (128x128x8, 256 thr, 8x8 micro) ------------------------- */
__device__ __forceinline__ void sgemm_body(
    const float* __restrict__ A, const float* __restrict__ B,
    float* __restrict__ C, const float* __restrict__ addC,
    int N, int K, int n0, const int* rows, int accumulate)
{
    __shared__ float As[8][128];
    __shared__ float Bs[8][128];

    int tid = threadIdx.x;
    int tx = tid & 15, ty = tid >> 4;
    int ar = tid >> 1, ac = (tid & 1) * 4;
    int br = tid >> 5, bc = (tid & 31) * 4;

    float acc[8][8];
#pragma unroll
    for (int i = 0; i < 8; i++)
#pragma unroll
        for (int jj = 0; jj < 8; jj++) acc[i][jj] = 0.f;

    int rowA = rows[ar];
    const float* Aptr = (rowA >= 0) ? (A + (size_t)rowA * K + ac) : 0;
    const float* Bptr = B + (size_t)br * N + n0 + bc;

    for (int k0 = 0; k0 < K; k0 += 8) {
        float4 av = Aptr ? *(const float4*)(Aptr + k0) : make_float4(0.f, 0.f, 0.f, 0.f);
        float4 bv = *(const float4*)(Bptr + (size_t)k0 * N);
        __syncthreads();
        As[ac + 0][ar] = av.x; As[ac + 1][ar] = av.y;
        As[ac + 2][ar] = av.z; As[ac + 3][ar] = av.w;
        Bs[br][bc + 0] = bv.x; Bs[br][bc + 1] = bv.y;
        Bs[br][bc + 2] = bv.z; Bs[br][bc + 3] = bv.w;
        __syncthreads();
#pragma unroll
        for (int kk = 0; kk < 8; kk++) {
            float a[8], b[8];
#pragma unroll
            for (int i = 0; i < 8; i++) a[i] = As[kk][ty * 8 + i];
#pragma unroll
            for (int i = 0; i < 8; i++) b[i] = Bs[kk][tx * 8 + i];
#pragma unroll
            for (int i = 0; i < 8; i++)
#pragma unroll
                for (int jj = 0; jj < 8; jj++)
                    acc[i][jj] = fmaf(a[i], b[jj], acc[i][jj]);
        }
    }
#pragma unroll
    for (int i = 0; i < 8; i++) {
        int gr = rows[ty * 8 + i];
        if (gr < 0) continue;
        size_t cb = (size_t)gr * N + n0 + tx * 8;
#pragma unroll
        for (int jj = 0; jj < 8; jj++) {
            float v = acc[i][jj];
            if (addC) v += addC[cb + jj];
            if (accumulate) C[cb + jj] += v;
            else C[cb + jj] = v;
        }
    }
}

__global__ void sgemm_kernel(const float* __restrict__ A, const float* __restrict__ B,
                             float* __restrict__ C, const float* __restrict__ addC,
                             int N, int K, int accumulate)
{
    __shared__ int rows[128];
    int m0 = blockIdx.y * 128;
    int n0 = blockIdx.x * 128;
    for (int i = threadIdx.x; i < 128; i += 256) rows[i] = m0 + i;
    __syncthreads();
    sgemm_body(A, B, C, addC, N, K, n0, rows, accumulate);
}

__global__ void sgemm_grouped_kernel(const float* __restrict__ A, const float* __restrict__ Bbase,
                                     size_t sB, float* __restrict__ C,
                                     int N, int K, int accumulate)
{
    int e = blockIdx.z;
    int cnt = g_cnt[e];
    int m0 = blockIdx.y * 128;
    if (m0 >= cnt) return;
    __shared__ int rows[128];
    int off = g_off[e];
    int n0 = blockIdx.x * 128;
    for (int i = threadIdx.x; i < 128; i += 256)
        rows[i] = (m0 + i < cnt) ? g_perm[off + m0 + i] : -1;
    __syncthreads();
    sgemm_body(A, Bbase + (size_t)e * sB, C, 0, N, K, n0, rows, accumulate);
}

/* ------------------------- router ------------------------- */
__global__ void router_kernel(const float* __restrict__ x2, const float* __restrict__ rw,
                              int* __restrict__ topidx, float* __restrict__ xw)
{
    int t = blockIdx.x, tid = threadIdx.x;
    size_t base = (size_t)t * H;
    float part[E];
#pragma unroll
    for (int e = 0; e < E; e++) part[e] = 0.f;
    for (int c = tid; c < H; c += 256) {
        float xv = x2[base + c];
#pragma unroll
        for (int e = 0; e < E; e++) part[e] = fmaf(xv, rw[c * E + e], part[e]);
    }
    __shared__ float red[256][E];
#pragma unroll
    for (int e = 0; e < E; e++) red[tid][e] = part[e];
    __syncthreads();
    for (int s = 128; s > 0; s >>= 1) {
        if (tid < s)
#pragma unroll
            for (int e = 0; e < E; e++) red[tid][e] += red[tid + s][e];
        __syncthreads();
    }
    __shared__ float s_scale;
    if (tid == 0) {
        float best = red[0][0]; int bi = 0;
        for (int e = 1; e < E; e++) if (red[0][e] > best) { best = red[0][e]; bi = e; }
        topidx[t] = bi;
        s_scale = 1.f / (1.f + expf(-best));
    }
    __syncthreads();
    float scv = s_scale;
    for (int c = tid; c < H; c += 256) xw[base + c] = x2[base + c] * scv;
}

/* ------------------------- expert histogram + permutation ------------------------- */
__global__ void hist_kernel()
{
    __shared__ int cnt[E], off[E], run[E];
    int tid = threadIdx.x;
    if (tid < E) { cnt[tid] = 0; run[tid] = 0; }
    __syncthreads();
    for (int t = tid; t < T; t += 256) atomicAdd(&cnt[g_topidx[t]], 1);
    __syncthreads();
    if (tid == 0) {
        int o = 0;
        for (int e = 0; e < E; e++) { off[e] = o; o += cnt[e]; }
    }
    __syncthreads();
    for (int t = tid; t < T; t += 256) {
        int e = g_topidx[t];
        int p = atomicAdd(&run[e], 1);
        g_perm[off[e] + p] = t;
    }
    __syncthreads();
    if (tid < E) { g_cnt[tid] = cnt[tid]; g_off[tid] = off[tid]; }
}

/* ------------------------- silu(g)*u (in place into g) ------------------------- */
__global__ void silu_mul_kernel(float* __restrict__ g, const float* __restrict__ u, int n)
{
    int i = blockIdx.x * 256 + threadIdx.x;
    if (i < n) {
        float gv = g[i];
        float sg = 1.f / (1.f + __expf(-gv));
        g[i] = gv * sg * u[i];
    }
}

/* ------------------------- launch ------------------------- */
extern "C" void kernel_launch(void* const* d_in, const int* in_sizes, int n_in,
                              void* d_out, int out_size)
{
    (void)in_sizes; (void)n_in; (void)out_size;
    const int*   positions = (const int*)d_in[0];
    const float* hidden    = (const float*)d_in[1];
    const float* residual  = (const float*)d_in[2];
    const float* ln1w      = (const float*)d_in[3];
    const float* ln2w      = (const float*)d_in[4];
    const float* w_qkv     = (const float*)d_in[5];
    const float* w_o       = (const float*)d_in[6];
    const float* router_w  = (const float*)d_in[7];
    const float* we_gate   = (const float*)d_in[8];
    const float* we_up     = (const float*)d_in[9];
    const float* we_down   = (const float*)d_in[10];
    const float* ws_gate   = (const float*)d_in[11];
    const float* ws_up     = (const float*)d_in[12];
    const float* ws_down   = (const float*)d_in[13];

    float* out  = (float*)d_out;
    float* res2 = out + (size_t)T * H;

    float *p_res, *p_x, *p_qkv, *p_attn, *p_xw, *p_g, *p_u;
    int *p_top;
    cudaGetSymbolAddress((void**)&p_res,  g_res);
    cudaGetSymbolAddress((void**)&p_x,    g_x);
    cudaGetSymbolAddress((void**)&p_qkv,  g_qkv);
    cudaGetSymbolAddress((void**)&p_attn, g_attn);
    cudaGetSymbolAddress((void**)&p_xw,   g_xw);
    cudaGetSymbolAddress((void**)&p_g,    g_gbuf);
    cudaGetSymbolAddress((void**)&p_u,    g_ubuf);
    cudaGetSymbolAddress((void**)&p_top,  g_topidx);

    /* 1. hs = hidden+residual ; res = hs ; x = rmsnorm(hs, ln1) */
    addnorm_kernel<<<T, 256>>>(hidden, residual, ln1w, p_res, p_x);
    /* 2. qkv = x @ w_qkv */
    sgemm_kernel<<<dim3(QKVW / 128, T / 128), 256>>>(p_x, w_qkv, p_qkv, 0, QKVW, H, 0);
    /* 3. rope + qk rmsnorm (in place) */
    rope_qknorm_kernel<<<dim3(T, NH + NKV), 128>>>(p_qkv, positions);
    /* 4. causal GQA attention */
    attn_kernel<<<dim3(T / 32, NH), 128>>>(p_qkv, p_attn);
    /* 5. res2 = attn @ w_o + res  (written directly into d_out second half) */
    sgemm_kernel<<<dim3(H / 128, T / 128), 256>>>(p_attn, w_o, res2, p_res, H, H, 0);
    /* 6. x2 = rmsnorm(res2, ln2)  (reuse g_x) */
    addnorm_kernel<<<T, 256>>>(res2, 0, ln2w, 0, p_x);
    /* 7. router: top-1 expert, score=sigmoid(top logit), xw = x2*score */
    router_kernel<<<T, 256>>>(p_x, router_w, p_top, p_xw);
    /* 8. group tokens by expert */
    hist_kernel<<<1, 256>>>();
    /* 9-12. shared expert: silu(x2@ws_gate)*(x2@ws_up) @ ws_down -> out */
    sgemm_kernel<<<dim3(I_DIM / 128, T / 128), 256>>>(p_x, ws_gate, p_g, 0, I_DIM, H, 0);
    sgemm_kernel<<<dim3(I_DIM / 128, T / 128), 256>>>(p_x, ws_up,   p_u, 0, I_DIM, H, 0);
    silu_mul_kernel<<<((size_t)T * I_DIM + 255) / 256, 256>>>(p_g, p_u, T * I_DIM);
    sgemm_kernel<<<dim3(H / 128, T / 128), 256>>>(p_g, ws_down, out, 0, H, I_DIM, 0);
    /* 13-16. routed expert (top-1, grouped): out += (silu(xw@We_g)*(xw@We_u)) @ We_d */
    sgemm_grouped_kernel<<<dim3(I_DIM / 128, T / 128, E), 256>>>(p_xw, we_gate, (size_t)H * I_DIM, p_g, I_DIM, H, 0);
    sgemm_grouped_kernel<<<dim3(I_DIM / 128, T / 128, E), 256>>>(p_xw, we_up,   (size_t)H * I_DIM, p_u, I_DIM, H, 0);
    silu_mul_kernel<<<((size_t)T * I_DIM + 255) / 256, 256>>>(p_g, p_u, T * I_DIM);
    sgemm_grouped_kernel<<<dim3(H / 128, T / 128, E), 256>>>(p_g, we_down, (size_t)I_DIM * H, out, H, I_DIM, 1);
}

// round 3
// speedup vs baseline: 1.4100x; 1.4100x over previous
#include <cuda_runtime.h>
#include <cuda_bf16.h>
#include <math.h>
#include <stdint.h>

#define T    2048
#define H    2048
#define NH   16
#define NKV  4
#define HD   128
#define E    8
#define I_DIM 4096
#define QKVW ((NH + 2*NKV) * HD)   /* 3072 */
#define EPSN 1e-5f
#define THETA_F 500000.0f
#define ATTN_SCALE 0.08838834764831845f

/* ===================== scratch (device globals) ===================== */
__device__ float g_res [T*H];
__device__ float g_x   [T*H];
__device__ float g_qkv [T*QKVW];
__device__ float g_attn[T*H];
__device__ float g_xw  [T*H];
__device__ float g_gbuf[(size_t)T*I_DIM];
__device__ float g_ubuf[(size_t)T*I_DIM];
__device__ int   g_topidx[T];
__device__ int   g_perm[T];
__device__ int   g_cnt[E];
__device__ int   g_off[E];

/* bf16 hi/lo weight copies, K-major transposed ([N][K]); uint4 = 8 bf16 */
__device__ uint4 b_qkv_hi[QKVW*H/8],      b_qkv_lo[QKVW*H/8];
__device__ uint4 b_o_hi  [H*H/8],         b_o_lo  [H*H/8];
__device__ uint4 b_wsg_hi[(size_t)I_DIM*H/8], b_wsg_lo[(size_t)I_DIM*H/8];
__device__ uint4 b_wsu_hi[(size_t)I_DIM*H/8], b_wsu_lo[(size_t)I_DIM*H/8];
__device__ uint4 b_wsd_hi[(size_t)H*I_DIM/8], b_wsd_lo[(size_t)H*I_DIM/8];
__device__ uint4 b_weg_hi[(size_t)E*I_DIM*H/8], b_weg_lo[(size_t)E*I_DIM*H/8];
__device__ uint4 b_weu_hi[(size_t)E*I_DIM*H/8], b_weu_lo[(size_t)E*I_DIM*H/8];
__device__ uint4 b_wed_hi[(size_t)E*H*I_DIM/8], b_wed_lo[(size_t)E*H*I_DIM/8];
__device__ uint4 g_ahi[(size_t)T*I_DIM/8], g_alo[(size_t)T*I_DIM/8];

/* ===================== small PTX wrappers ===================== */
__device__ __forceinline__ uint32_t smem_u32(const void* p) {
    uint32_t a;
    asm("{ .reg .u64 t; cvta.to.shared.u64 t, %1; cvt.u32.u64 %0, t; }" : "=r"(a) : "l"(p));
    return a;
}
__device__ __forceinline__ void ldm4(uint32_t* r, uint32_t addr) {
    asm volatile("ldmatrix.sync.aligned.m8n8.x4.shared.b16 {%0,%1,%2,%3}, [%4];"
        : "=r"(r[0]), "=r"(r[1]), "=r"(r[2]), "=r"(r[3]) : "r"(addr));
}
__device__ __forceinline__ void mma_bf16(float* c, const uint32_t* a, const uint32_t* b) {
    asm volatile(
        "mma.sync.aligned.m16n8k16.row.col.f32.bf16.bf16.f32 "
        "{%0,%1,%2,%3}, {%4,%5,%6,%7}, {%8,%9}, {%0,%1,%2,%3};"
        : "+f"(c[0]), "+f"(c[1]), "+f"(c[2]), "+f"(c[3])
        : "r"(a[0]), "r"(a[1]), "r"(a[2]), "r"(a[3]), "r"(b[0]), "r"(b[1]));
}
#define CP16(dst, src, sz) asm volatile("cp.async.cg.shared.global [%0], [%1], 16, %2;" :: "r"(dst), "l"(src), "r"(sz) : "memory")

/* ===================== add + rmsnorm ===================== */
__global__ void addnorm_kernel(const float* __restrict__ a, const float* __restrict__ b,
                               const float* __restrict__ w, float* __restrict__ res,
                               float* __restrict__ xout)
{
    int t = blockIdx.x;
    int tid = threadIdx.x;
    const int PER = H / 256;
    size_t base = (size_t)t * H;
    float v[PER];
    float ss = 0.f;
#pragma unroll
    for (int u = 0; u < PER; u++) {
        int c = tid + u * 256;
        float val = a[base + c];
        if (b) val += b[base + c];
        v[u] = val;
        if (res) res[base + c] = val;
        ss += val * val;
    }
    __shared__ float red[256];
    red[tid] = ss;
    __syncthreads();
    for (int s = 128; s > 0; s >>= 1) {
        if (tid < s) red[tid] += red[tid + s];
        __syncthreads();
    }
    float scale = rsqrtf(red[0] / (float)H + EPSN);
#pragma unroll
    for (int u = 0; u < PER; u++) {
        int c = tid + u * 256;
        xout[base + c] = v[u] * scale * w[c];
    }
}

/* ===================== rope + q/k rmsnorm ===================== */
__global__ void rope_qknorm_kernel(float* __restrict__ qkv, const int* __restrict__ positions)
{
    int t  = blockIdx.x;
    int hh = blockIdx.y;
    int col0 = (hh < NH) ? hh * HD : (NH * HD + (hh - NH) * HD);
    float* p = qkv + (size_t)t * QKVW + col0;
    int d = threadIdx.x;
    float pos = (float)positions[t];
    int i = (d < 64) ? d : d - 64;
    float invf = powf(THETA_F, -(float)i / 64.f);
    float ang = pos * invf;
    float c = cosf(ang), s = sinf(ang);
    float x1 = p[i], x2 = p[i + 64];
    float val = (d < 64) ? (x1 * c - x2 * s) : (x2 * c + x1 * s);

    __shared__ float red[128];
    red[d] = val * val;
    __syncthreads();
    for (int st = 64; st > 0; st >>= 1) {
        if (d < st) red[d] += red[d + st];
        __syncthreads();
    }
    float scale = rsqrtf(red[0] / (float)HD + EPSN);
    p[d] = val * scale;
}

/* ===================== flash attention (causal, GQA) ===================== */
__global__ void attn_kernel(const float* __restrict__ qkv, float* __restrict__ out)
{
    int qb = blockIdx.x;
    int h  = blockIdx.y;
    int tid = threadIdx.x;
    int r = tid >> 2;
    int j = tid & 3;
    int qt = qb * 32 + r;
    int kvh = h >> 2;

    const float* qptr = qkv + (size_t)qt * QKVW + h * HD + j * 32;
    float qreg[32];
#pragma unroll
    for (int d = 0; d < 32; d++) qreg[d] = qptr[d];

    __shared__ float Ks[32][128];
    __shared__ float Vs[32][128];

    float m = -1e30f, l = 0.f;
    float acc[32];
#pragma unroll
    for (int d = 0; d < 32; d++) acc[d] = 0.f;

    for (int kt = 0; kt <= qb; kt++) {
        for (int li = tid; li < 32 * 128; li += 128) {
            int row = li >> 7, col = li & 127;
            size_t gb = (size_t)(kt * 32 + row) * QKVW + kvh * HD + col;
            Ks[row][col] = qkv[gb + NH * HD];
            Vs[row][col] = qkv[gb + (NH + NKV) * HD];
        }
        __syncthreads();

        float sc[32];
#pragma unroll 4
        for (int c = 0; c < 32; c++) {
            float a4 = 0.f;
#pragma unroll
            for (int d = 0; d < 32; d++) a4 = fmaf(qreg[d], Ks[c][j * 32 + d], a4);
            sc[c] = a4;
        }
#pragma unroll
        for (int c = 0; c < 32; c++) {
            sc[c] += __shfl_xor_sync(0xffffffffu, sc[c], 1);
            sc[c] += __shfl_xor_sync(0xffffffffu, sc[c], 2);
            int ka = kt * 32 + c;
            sc[c] = (ka <= qt) ? sc[c] * ATTN_SCALE : -1e30f;
        }
        float mt = -1e30f;
#pragma unroll
        for (int c = 0; c < 32; c++) mt = fmaxf(mt, sc[c]);
        float mnew = fmaxf(m, mt);
        float alpha = __expf(m - mnew);
        float psum = 0.f;
#pragma unroll
        for (int c = 0; c < 32; c++) { sc[c] = __expf(sc[c] - mnew); psum += sc[c]; }
        l = l * alpha + psum;
        m = mnew;
#pragma unroll
        for (int d = 0; d < 32; d++) acc[d] *= alpha;
#pragma unroll 4
        for (int c = 0; c < 32; c++) {
            float pc = sc[c];
#pragma unroll
            for (int d = 0; d < 32; d++) acc[d] = fmaf(pc, Vs[c][j * 32 + d], acc[d]);
        }
        __syncthreads();
    }
    float inv = 1.f / l;
    float* op = out + (size_t)qt * H + h * HD + j * 32;
#pragma unroll
    for (int d = 0; d < 32; d++) op[d] = acc[d] * inv;
}

/* ===================== fp32 -> bf16 hi/lo (activations) ===================== */
__global__ void cvt_act_kernel(const float4* __restrict__ x,
                               __nv_bfloat162* __restrict__ hi,
                               __nv_bfloat162* __restrict__ lo, int n4)
{
    int i = blockIdx.x * 256 + threadIdx.x;
    if (i >= n4) return;
    float4 v = x[i];
    __nv_bfloat16 h0 = __float2bfloat16(v.x), h1 = __float2bfloat16(v.y);
    __nv_bfloat16 h2 = __float2bfloat16(v.z), h3 = __float2bfloat16(v.w);
    __nv_bfloat16 l0 = __float2bfloat16(v.x - __bfloat162float(h0));
    __nv_bfloat16 l1 = __float2bfloat16(v.y - __bfloat162float(h1));
    __nv_bfloat16 l2 = __float2bfloat16(v.z - __bfloat162float(h2));
    __nv_bfloat16 l3 = __float2bfloat16(v.w - __bfloat162float(h3));
    hi[2*i]   = __halves2bfloat162(h0, h1);
    hi[2*i+1] = __halves2bfloat162(h2, h3);
    lo[2*i]   = __halves2bfloat162(l0, l1);
    lo[2*i+1] = __halves2bfloat162(l2, l3);
}

/* ===================== fp32 W[K][N] -> bf16 hi/lo [N][K] ===================== */
__global__ void cvt_wT_kernel(const float* __restrict__ W,
                              __nv_bfloat16* __restrict__ bhi,
                              __nv_bfloat16* __restrict__ blo, int Kd, int Nd)
{
    __shared__ float t[32][33];
    size_t zoff = (size_t)blockIdx.z * Kd * Nd;
    W += zoff; bhi += zoff; blo += zoff;
    int n0 = blockIdx.x * 32, k0 = blockIdx.y * 32;
    int tx = threadIdx.x, ty = threadIdx.y;
#pragma unroll
    for (int r = ty; r < 32; r += 8)
        t[r][tx] = W[(size_t)(k0 + r) * Nd + n0 + tx];
    __syncthreads();
#pragma unroll
    for (int r = ty; r < 32; r += 8) {
        float v = t[tx][r];
        __nv_bfloat16 h = __float2bfloat16(v);
        __nv_bfloat16 l = __float2bfloat16(v - __bfloat162float(h));
        size_t o = (size_t)(n0 + r) * Kd + k0 + tx;
        bhi[o] = h;
        blo[o] = l;
    }
}

/* ===================== tensor-core split-bf16 GEMM (mma.sync) =====================
 * C[M,N] = A[M,K] @ W[K,N], W pre-transposed [N][K] hi/lo.
 * CTA: 128x128, BK=32, 2-stage cp.async. 8 warps = 4(m) x 2(n); warp: 32x64.
 * 3 mma terms per fragment: AhiBhi + AhiBlo + AloBhi (fp32 accum).
 * Smem rows padded to 80B (conflict-free ldmatrix).
 * grouped: rows gathered via g_perm per expert (blockIdx.z). */
#define ROWB 80
#define STAGE_BYTES (4 * 128 * ROWB)   /* 40960 */
#define GSMEM (512 + 2 * STAGE_BYTES)  /* 82432 */

__global__ __launch_bounds__(256, 1) void mma_gemm_kernel(
    const uint4* __restrict__ Ahi4, const uint4* __restrict__ Alo4,
    const uint4* __restrict__ Bhi4, const uint4* __restrict__ Blo4,
    float* __restrict__ C, const float* __restrict__ addC,
    int N, int K, int accumulate, int grouped)
{
    extern __shared__ __align__(16) char smem[];
    const int tid = threadIdx.x;
    const int wid = tid >> 5;
    const int lane = tid & 31;
    const int warp_m = wid >> 1;
    const int warp_n = wid & 1;
    const int n0 = blockIdx.x * 128;
    const int m0 = blockIdx.y * 128;

    if (grouped) {
        int cnt = g_cnt[blockIdx.z];
        if (m0 >= cnt) return;
        size_t bstride = ((size_t)N * K) >> 3;
        Bhi4 += (size_t)blockIdx.z * bstride;
        Blo4 += (size_t)blockIdx.z * bstride;
    }
    int* rows = (int*)smem;
    {
        int cnt = grouped ? g_cnt[blockIdx.z] : 0;
        int off = grouped ? g_off[blockIdx.z] : 0;
        for (int i = tid; i < 128; i += 256)
            rows[i] = grouped ? ((m0 + i < cnt) ? g_perm[off + m0 + i] : -1) : (m0 + i);
    }
    __syncthreads();

    const uint32_t sb = smem_u32(smem);
    const int K8 = K >> 3;            /* uint4 per row */
    const int nch = K >> 5;           /* K chunks of 32 */

    /* ---- load geometry: thread t -> row t>>1, two 16B chunks (t&1)*2, +1 ---- */
    const int lrow = tid >> 1;
    const int c0 = (tid & 1) * 2;
    int ra = rows[lrow];
    uint32_t szA = (ra >= 0) ? 16u : 0u;
    size_t ibA = (size_t)(ra >= 0 ? ra : 0) * K8 + c0;
    size_t ibB = (size_t)(n0 + lrow) * K8 + c0;
    uint32_t dof = (uint32_t)(lrow * ROWB + c0 * 16);

    /* ---- ldmatrix address bases ---- */
    /* A: lanes 0-15 -> rows, lanes 16-31 -> rows with col+8 */
    uint32_t aRowOff = (uint32_t)((warp_m * 32 + (lane & 15)) * ROWB + ((lane >> 4) * 8) * 2);
    /* B x4 covers 2 n-tiles: g=lane>>3: n_off=(g>>1)*8, k_off=(g&1)*8 */
    int g = lane >> 3;
    uint32_t bRowOff = (uint32_t)((warp_n * 64 + (g >> 1) * 8 + (lane & 7)) * ROWB + ((g & 1) * 8) * 2);

    float acc[2][8][4];
#pragma unroll
    for (int mt = 0; mt < 2; mt++)
#pragma unroll
        for (int nt = 0; nt < 8; nt++)
#pragma unroll
            for (int q = 0; q < 4; q++) acc[mt][nt][q] = 0.f;

    /* stage base offsets */
    auto stageA_hi = [&](int s) { return sb + 512 + s * STAGE_BYTES; };

    /* ---- prologue: load chunk 0 into stage 0 ---- */
    {
        uint32_t tb = stageA_hi(0);
        CP16(tb + dof,                 (const void*)(Ahi4 + ibA), szA);
        CP16(tb + 10240 + dof,         (const void*)(Alo4 + ibA), szA);
        CP16(tb + 20480 + dof,         (const void*)(Bhi4 + ibB), 16u);
        CP16(tb + 30720 + dof,         (const void*)(Blo4 + ibB), 16u);
        CP16(tb + dof + 16,            (const void*)(Ahi4 + ibA + 1), szA);
        CP16(tb + 10240 + dof + 16,    (const void*)(Alo4 + ibA + 1), szA);
        CP16(tb + 20480 + dof + 16,    (const void*)(Bhi4 + ibB + 1), 16u);
        CP16(tb + 30720 + dof + 16,    (const void*)(Blo4 + ibB + 1), 16u);
        asm volatile("cp.async.commit_group;" ::: "memory");
    }

    for (int c = 0; c < nch; c++) {
        if (c + 1 < nch) {
            uint32_t tb = stageA_hi((c + 1) & 1);
            size_t ko = (size_t)(c + 1) * 4;
            CP16(tb + dof,              (const void*)(Ahi4 + ibA + ko), szA);
            CP16(tb + 10240 + dof,      (const void*)(Alo4 + ibA + ko), szA);
            CP16(tb + 20480 + dof,      (const void*)(Bhi4 + ibB + ko), 16u);
            CP16(tb + 30720 + dof,      (const void*)(Blo4 + ibB + ko), 16u);
            CP16(tb + dof + 16,         (const void*)(Ahi4 + ibA + ko + 1), szA);
            CP16(tb + 10240 + dof + 16, (const void*)(Alo4 + ibA + ko + 1), szA);
            CP16(tb + 20480 + dof + 16, (const void*)(Bhi4 + ibB + ko + 1), 16u);
            CP16(tb + 30720 + dof + 16, (const void*)(Blo4 + ibB + ko + 1), 16u);
        }
        asm volatile("cp.async.commit_group;" ::: "memory");
        asm volatile("cp.async.wait_group 1;" ::: "memory");
        __syncthreads();

        uint32_t aHi = stageA_hi(c & 1);
        uint32_t aLo = aHi + 10240;
        uint32_t bHi = aHi + 20480;
        uint32_t bLo = aHi + 30720;

#pragma unroll
        for (int kk = 0; kk < 2; kk++) {
            uint32_t ah[2][4], al_[2][4];
            ldm4(ah[0],  aHi + aRowOff + kk * 32);
            ldm4(ah[1],  aHi + aRowOff + 1280 + kk * 32);
            ldm4(al_[0], aLo + aRowOff + kk * 32);
            ldm4(al_[1], aLo + aRowOff + 1280 + kk * 32);
            uint32_t bh[4][4], bl[4][4];
#pragma unroll
            for (int p = 0; p < 4; p++) {
                ldm4(bh[p], bHi + bRowOff + p * 1280 + kk * 32);
                ldm4(bl[p], bLo + bRowOff + p * 1280 + kk * 32);
            }
#pragma unroll
            for (int mt = 0; mt < 2; mt++) {
#pragma unroll
                for (int p = 0; p < 4; p++) {
#pragma unroll
                    for (int hh = 0; hh < 2; hh++) {
                        int nt = p * 2 + hh;
                        mma_bf16(acc[mt][nt], ah[mt],  &bh[p][hh * 2]);
                        mma_bf16(acc[mt][nt], ah[mt],  &bl[p][hh * 2]);
                        mma_bf16(acc[mt][nt], al_[mt], &bh[p][hh * 2]);
                    }
                }
            }
        }
        __syncthreads();
    }

    /* ---- epilogue ---- */
    int lr = lane >> 2, lc = (lane & 3) * 2;
#pragma unroll
    for (int mt = 0; mt < 2; mt++) {
        int rloc = warp_m * 32 + mt * 16 + lr;
        int grow0 = rows[rloc];
        int grow1 = rows[rloc + 8];
#pragma unroll
        for (int nt = 0; nt < 8; nt++) {
            int col = n0 + warp_n * 64 + nt * 8 + lc;
            float* a4 = acc[mt][nt];
            if (grow0 >= 0) {
                size_t cb = (size_t)grow0 * N + col;
                if (accumulate) { C[cb] += a4[0]; C[cb + 1] += a4[1]; }
                else if (addC)  { C[cb] = a4[0] + addC[cb]; C[cb + 1] = a4[1] + addC[cb + 1]; }
                else            { C[cb] = a4[0]; C[cb + 1] = a4[1]; }
            }
            if (grow1 >= 0) {
                size_t cb = (size_t)grow1 * N + col;
                if (accumulate) { C[cb] += a4[2]; C[cb + 1] += a4[3]; }
                else if (addC)  { C[cb] = a4[2] + addC[cb]; C[cb + 1] = a4[3] + addC[cb + 1]; }
                else            { C[cb] = a4[2]; C[cb + 1] = a4[3]; }
            }
        }
    }
}

/* ===================== router ===================== */
__global__ void router_kernel(const float* __restrict__ x2, const float* __restrict__ rw,
                              int* __restrict__ topidx, float* __restrict__ xw)
{
    int t = blockIdx.x, tid = threadIdx.x;
    size_t base = (size_t)t * H;
    float part[E];
#pragma unroll
    for (int e = 0; e < E; e++) part[e] = 0.f;
    for (int c = tid; c < H; c += 256) {
        float xv = x2[base + c];
#pragma unroll
        for (int e = 0; e < E; e++) part[e] = fmaf(xv, rw[c * E + e], part[e]);
    }
    __shared__ float red[256][E];
#pragma unroll
    for (int e = 0; e < E; e++) red[tid][e] = part[e];
    __syncthreads();
    for (int s = 128; s > 0; s >>= 1) {
        if (tid < s)
#pragma unroll
            for (int e = 0; e < E; e++) red[tid][e] += red[tid + s][e];
        __syncthreads();
    }
    __shared__ float s_scale;
    if (tid == 0) {
        float best = red[0][0]; int bi = 0;
        for (int e = 1; e < E; e++) if (red[0][e] > best) { best = red[0][e]; bi = e; }
        topidx[t] = bi;
        s_scale = 1.f / (1.f + expf(-best));
    }
    __syncthreads();
    float scv = s_scale;
    for (int c = tid; c < H; c += 256) xw[base + c] = x2[base + c] * scv;
}

/* ===================== expert histogram + permutation ===================== */
__global__ void hist_kernel()
{
    __shared__ int cnt[E], off[E], run[E];
    int tid = threadIdx.x;
    if (tid < E) { cnt[tid] = 0; run[tid] = 0; }
    __syncthreads();
    for (int t = tid; t < T; t += 256) atomicAdd(&cnt[g_topidx[t]], 1);
    __syncthreads();
    if (tid == 0) {
        int o = 0;
        for (int e = 0; e < E; e++) { off[e] = o; o += cnt[e]; }
    }
    __syncthreads();
    for (int t = tid; t < T; t += 256) {
        int e = g_topidx[t];
        int p = atomicAdd(&run[e], 1);
        g_perm[off[e] + p] = t;
    }
    __syncthreads();
    if (tid < E) { g_cnt[tid] = cnt[tid]; g_off[tid] = off[tid]; }
}

/* ===================== silu(g)*u ===================== */
__global__ void silu_mul_kernel(float* __restrict__ g, const float* __restrict__ u, int n)
{
    int i = blockIdx.x * 256 + threadIdx.x;
    if (i < n) {
        float gv = g[i];
        float sg = 1.f / (1.f + __expf(-gv));
        g[i] = gv * sg * u[i];
    }
}

/* ===================== launch ===================== */
extern "C" void kernel_launch(void* const* d_in, const int* in_sizes, int n_in,
                              void* d_out, int out_size)
{
    (void)in_sizes; (void)n_in; (void)out_size;
    const int*   positions = (const int*)d_in[0];
    const float* hidden    = (const float*)d_in[1];
    const float* residual  = (const float*)d_in[2];
    const float* ln1w      = (const float*)d_in[3];
    const float* ln2w      = (const float*)d_in[4];
    const float* w_qkv     = (const float*)d_in[5];
    const float* w_o       = (const float*)d_in[6];
    const float* router_w  = (const float*)d_in[7];
    const float* we_gate   = (const float*)d_in[8];
    const float* we_up     = (const float*)d_in[9];
    const float* we_down   = (const float*)d_in[10];
    const float* ws_gate   = (const float*)d_in[11];
    const float* ws_up     = (const float*)d_in[12];
    const float* ws_down   = (const float*)d_in[13];

    float* out  = (float*)d_out;
    float* res2 = out + (size_t)T * H;

    float *p_res, *p_x, *p_qkv, *p_attn, *p_xw, *p_g, *p_u;
    int *p_top;
    uint4 *qh, *ql, *oh, *ol, *sgh, *sgl, *suh, *sul, *sdh, *sdl;
    uint4 *egh, *egl, *euh, *eul, *edh, *edl, *ah, *al;
    cudaGetSymbolAddress((void**)&p_res,  g_res);
    cudaGetSymbolAddress((void**)&p_x,    g_x);
    cudaGetSymbolAddress((void**)&p_qkv,  g_qkv);
    cudaGetSymbolAddress((void**)&p_attn, g_attn);
    cudaGetSymbolAddress((void**)&p_xw,   g_xw);
    cudaGetSymbolAddress((void**)&p_g,    g_gbuf);
    cudaGetSymbolAddress((void**)&p_u,    g_ubuf);
    cudaGetSymbolAddress((void**)&p_top,  g_topidx);
    cudaGetSymbolAddress((void**)&qh,  b_qkv_hi); cudaGetSymbolAddress((void**)&ql,  b_qkv_lo);
    cudaGetSymbolAddress((void**)&oh,  b_o_hi);   cudaGetSymbolAddress((void**)&ol,  b_o_lo);
    cudaGetSymbolAddress((void**)&sgh, b_wsg_hi); cudaGetSymbolAddress((void**)&sgl, b_wsg_lo);
    cudaGetSymbolAddress((void**)&suh, b_wsu_hi); cudaGetSymbolAddress((void**)&sul, b_wsu_lo);
    cudaGetSymbolAddress((void**)&sdh, b_wsd_hi); cudaGetSymbolAddress((void**)&sdl, b_wsd_lo);
    cudaGetSymbolAddress((void**)&egh, b_weg_hi); cudaGetSymbolAddress((void**)&egl, b_weg_lo);
    cudaGetSymbolAddress((void**)&euh, b_weu_hi); cudaGetSymbolAddress((void**)&eul, b_weu_lo);
    cudaGetSymbolAddress((void**)&edh, b_wed_hi); cudaGetSymbolAddress((void**)&edl, b_wed_lo);
    cudaGetSymbolAddress((void**)&ah,  g_ahi);    cudaGetSymbolAddress((void**)&al,  g_alo);

    cudaFuncSetAttribute(mma_gemm_kernel, cudaFuncAttributeMaxDynamicSharedMemorySize, GSMEM);

    dim3 tb(32, 8);
    cvt_wT_kernel<<<dim3(QKVW/32, H/32, 1), tb>>>(w_qkv, (__nv_bfloat16*)qh, (__nv_bfloat16*)ql, H, QKVW);
    cvt_wT_kernel<<<dim3(H/32, H/32, 1), tb>>>(w_o, (__nv_bfloat16*)oh, (__nv_bfloat16*)ol, H, H);
    cvt_wT_kernel<<<dim3(I_DIM/32, H/32, 1), tb>>>(ws_gate, (__nv_bfloat16*)sgh, (__nv_bfloat16*)sgl, H, I_DIM);
    cvt_wT_kernel<<<dim3(I_DIM/32, H/32, 1), tb>>>(ws_up,   (__nv_bfloat16*)suh, (__nv_bfloat16*)sul, H, I_DIM);
    cvt_wT_kernel<<<dim3(H/32, I_DIM/32, 1), tb>>>(ws_down, (__nv_bfloat16*)sdh, (__nv_bfloat16*)sdl, I_DIM, H);
    cvt_wT_kernel<<<dim3(I_DIM/32, H/32, E), tb>>>(we_gate, (__nv_bfloat16*)egh, (__nv_bfloat16*)egl, H, I_DIM);
    cvt_wT_kernel<<<dim3(I_DIM/32, H/32, E), tb>>>(we_up,   (__nv_bfloat16*)euh, (__nv_bfloat16*)eul, H, I_DIM);
    cvt_wT_kernel<<<dim3(H/32, I_DIM/32, E), tb>>>(we_down, (__nv_bfloat16*)edh, (__nv_bfloat16*)edl, I_DIM, H);

    /* 1. hs = hidden+residual ; res ; x = rmsnorm */
    addnorm_kernel<<<T, 256>>>(hidden, residual, ln1w, p_res, p_x);
    /* 2. qkv = x @ w_qkv */
    cvt_act_kernel<<<(T*H/4 + 255)/256, 256>>>((const float4*)p_x, (__nv_bfloat162*)ah, (__nv_bfloat162*)al, T*H/4);
    mma_gemm_kernel<<<dim3(QKVW/128, T/128, 1), 256, GSMEM>>>(ah, al, qh, ql, p_qkv, 0, QKVW, H, 0, 0);
    /* 3-4. rope + attention */
    rope_qknorm_kernel<<<dim3(T, NH + NKV), 128>>>(p_qkv, positions);
    attn_kernel<<<dim3(T / 32, NH), 128>>>(p_qkv, p_attn);
    /* 5. res2 = attn @ w_o + res */
    cvt_act_kernel<<<(T*H/4 + 255)/256, 256>>>((const float4*)p_attn, (__nv_bfloat162*)ah, (__nv_bfloat162*)al, T*H/4);
    mma_gemm_kernel<<<dim3(H/128, T/128, 1), 256, GSMEM>>>(ah, al, oh, ol, res2, p_res, H, H, 0, 0);
    /* 6. x2 = rmsnorm(res2) */
    addnorm_kernel<<<T, 256>>>(res2, 0, ln2w, 0, p_x);
    /* 7-8. router + grouping */
    router_kernel<<<T, 256>>>(p_x, router_w, p_top, p_xw);
    hist_kernel<<<1, 256>>>();
    /* 9-12. shared expert */
    cvt_act_kernel<<<(T*H/4 + 255)/256, 256>>>((const float4*)p_x, (__nv_bfloat162*)ah, (__nv_bfloat162*)al, T*H/4);
    mma_gemm_kernel<<<dim3(I_DIM/128, T/128, 1), 256, GSMEM>>>(ah, al, sgh, sgl, p_g, 0, I_DIM, H, 0, 0);
    mma_gemm_kernel<<<dim3(I_DIM/128, T/128, 1), 256, GSMEM>>>(ah, al, suh, sul, p_u, 0, I_DIM, H, 0, 0);
    silu_mul_kernel<<<((size_t)T * I_DIM + 255) / 256, 256>>>(p_g, p_u, T * I_DIM);
    cvt_act_kernel<<<((size_t)T*I_DIM/4 + 255)/256, 256>>>((const float4*)p_g, (__nv_bfloat162*)ah, (__nv_bfloat162*)al, T*I_DIM/4);
    mma_gemm_kernel<<<dim3(H/128, T/128, 1), 256, GSMEM>>>(ah, al, sdh, sdl, out, 0, H, I_DIM, 0, 0);
    /* 13-16. routed expert (top-1, grouped) */
    cvt_act_kernel<<<(T*H/4 + 255)/256, 256>>>((const float4*)p_xw, (__nv_bfloat162*)ah, (__nv_bfloat162*)al, T*H/4);
    mma_gemm_kernel<<<dim3(I_DIM/128, T/128, E), 256, GSMEM>>>(ah, al, egh, egl, p_g, 0, I_DIM, H, 0, 1);
    mma_gemm_kernel<<<dim3(I_DIM/128, T/128, E), 256, GSMEM>>>(ah, al, euh, eul, p_u, 0, I_DIM, H, 0, 1);
    silu_mul_kernel<<<((size_t)T * I_DIM + 255) / 256, 256>>>(p_g, p_u, T * I_DIM);
    cvt_act_kernel<<<((size_t)T*I_DIM/4 + 255)/256, 256>>>((const float4*)p_g, (__nv_bfloat162*)ah, (__nv_bfloat162*)al, T*I_DIM/4);
    mma_gemm_kernel<<<dim3(H/128, T/128, E), 256, GSMEM>>>(ah, al, edh, edl, out, 0, H, I_DIM, 1, 1);
}

// round 4
// speedup vs baseline: 1.7291x; 1.2263x over previous
#include <cuda_runtime.h>
#include <cuda_fp16.h>
#include <math.h>
#include <stdint.h>

#define T    2048
#define H    2048
#define NH   16
#define NKV  4
#define HD   128
#define E    8
#define I_DIM 4096
#define QKVW ((NH + 2*NKV) * HD)   /* 3072 */
#define EPSN 1e-5f
#define THETA_F 500000.0f
#define ATTN_SCALE 0.08838834764831845f

/* ===================== scratch (device globals) ===================== */
__device__ float g_res [T*H];
__device__ float g_x   [T*H];      /* x2 fp32 for router */
__device__ float g_qkv [T*QKVW];
__device__ float g_gbuf[(size_t)T*I_DIM];
__device__ float g_ubuf[(size_t)T*I_DIM];
__device__ int   g_topidx[T];
__device__ int   g_perm[T];
__device__ int   g_cnt[E];
__device__ int   g_off[E];

/* fp16 weights, K-major transposed [N][K]; uint4 = 8 halves */
__device__ uint4 b_qkv[QKVW*H/8];
__device__ uint4 b_o  [H*H/8];
__device__ uint4 b_wsg[(size_t)I_DIM*H/8];
__device__ uint4 b_wsu[(size_t)I_DIM*H/8];
__device__ uint4 b_wsd[(size_t)H*I_DIM/8];
__device__ uint4 b_weg[(size_t)E*I_DIM*H/8];
__device__ uint4 b_weu[(size_t)E*I_DIM*H/8];
__device__ uint4 b_wed[(size_t)E*H*I_DIM/8];
/* fp16 activations */
__device__ uint4 g_act1[(size_t)T*I_DIM/8];   /* x / attn / x2 / silu-g */
__device__ uint4 g_act2[(size_t)T*H/8];       /* xw (routed-expert input) */

/* ===================== small PTX wrappers ===================== */
__device__ __forceinline__ uint32_t smem_u32(const void* p) {
    uint32_t a;
    asm("{ .reg .u64 t; cvta.to.shared.u64 t, %1; cvt.u32.u64 %0, t; }" : "=r"(a) : "l"(p));
    return a;
}
__device__ __forceinline__ void ldm4(uint32_t* r, uint32_t addr) {
    asm volatile("ldmatrix.sync.aligned.m8n8.x4.shared.b16 {%0,%1,%2,%3}, [%4];"
        : "=r"(r[0]), "=r"(r[1]), "=r"(r[2]), "=r"(r[3]) : "r"(addr));
}
__device__ __forceinline__ void mma_f16(float* c, const uint32_t* a, const uint32_t* b) {
    asm volatile(
        "mma.sync.aligned.m16n8k16.row.col.f32.f16.f16.f32 "
        "{%0,%1,%2,%3}, {%4,%5,%6,%7}, {%8,%9}, {%0,%1,%2,%3};"
        : "+f"(c[0]), "+f"(c[1]), "+f"(c[2]), "+f"(c[3])
        : "r"(a[0]), "r"(a[1]), "r"(a[2]), "r"(a[3]), "r"(b[0]), "r"(b[1]));
}
#define CP16(dst, src, sz) asm volatile("cp.async.cg.shared.global [%0], [%1], 16, %2;" :: "r"(dst), "l"(src), "r"(sz) : "memory")

/* ===================== add + rmsnorm (fp32 opt + fp16 out) ===================== */
__global__ void addnorm_kernel(const float* __restrict__ a, const float* __restrict__ b,
                               const float* __restrict__ w, float* __restrict__ res,
                               float* __restrict__ xout, __half* __restrict__ xh)
{
    int t = blockIdx.x;
    int tid = threadIdx.x;
    const int PER = H / 256;
    size_t base = (size_t)t * H;
    float v[PER];
    float ss = 0.f;
#pragma unroll
    for (int u = 0; u < PER; u++) {
        int c = tid + u * 256;
        float val = a[base + c];
        if (b) val += b[base + c];
        v[u] = val;
        if (res) res[base + c] = val;
        ss += val * val;
    }
    __shared__ float red[256];
    red[tid] = ss;
    __syncthreads();
    for (int s = 128; s > 0; s >>= 1) {
        if (tid < s) red[tid] += red[tid + s];
        __syncthreads();
    }
    float scale = rsqrtf(red[0] / (float)H + EPSN);
#pragma unroll
    for (int u = 0; u < PER; u++) {
        int c = tid + u * 256;
        float o = v[u] * scale * w[c];
        if (xout) xout[base + c] = o;
        xh[base + c] = __float2half(o);
    }
}

/* ===================== rope + q/k rmsnorm ===================== */
__global__ void rope_qknorm_kernel(float* __restrict__ qkv, const int* __restrict__ positions)
{
    int t  = blockIdx.x;
    int hh = blockIdx.y;
    int col0 = (hh < NH) ? hh * HD : (NH * HD + (hh - NH) * HD);
    float* p = qkv + (size_t)t * QKVW + col0;
    int d = threadIdx.x;
    float pos = (float)positions[t];
    int i = (d < 64) ? d : d - 64;
    float invf = powf(THETA_F, -(float)i / 64.f);
    float ang = pos * invf;
    float c = cosf(ang), s = sinf(ang);
    float x1 = p[i], x2 = p[i + 64];
    float val = (d < 64) ? (x1 * c - x2 * s) : (x2 * c + x1 * s);

    __shared__ float red[128];
    red[d] = val * val;
    __syncthreads();
    for (int st = 64; st > 0; st >>= 1) {
        if (d < st) red[d] += red[d + st];
        __syncthreads();
    }
    float scale = rsqrtf(red[0] / (float)HD + EPSN);
    p[d] = val * scale;
}

/* ===================== flash attention (causal, GQA), fp16 out ===================== */
__global__ void attn_kernel(const float* __restrict__ qkv, __half* __restrict__ out)
{
    int qb = blockIdx.x;
    int h  = blockIdx.y;
    int tid = threadIdx.x;
    int r = tid >> 2;
    int j = tid & 3;
    int qt = qb * 32 + r;
    int kvh = h >> 2;

    const float* qptr = qkv + (size_t)qt * QKVW + h * HD + j * 32;
    float qreg[32];
#pragma unroll
    for (int d = 0; d < 32; d++) qreg[d] = qptr[d];

    __shared__ float Ks[32][128];
    __shared__ float Vs[32][128];

    float m = -1e30f, l = 0.f;
    float acc[32];
#pragma unroll
    for (int d = 0; d < 32; d++) acc[d] = 0.f;

    for (int kt = 0; kt <= qb; kt++) {
        for (int li = tid; li < 32 * 128; li += 128) {
            int row = li >> 7, col = li & 127;
            size_t gb = (size_t)(kt * 32 + row) * QKVW + kvh * HD + col;
            Ks[row][col] = qkv[gb + NH * HD];
            Vs[row][col] = qkv[gb + (NH + NKV) * HD];
        }
        __syncthreads();

        float sc[32];
#pragma unroll 4
        for (int c = 0; c < 32; c++) {
            float a4 = 0.f;
#pragma unroll
            for (int d = 0; d < 32; d++) a4 = fmaf(qreg[d], Ks[c][j * 32 + d], a4);
            sc[c] = a4;
        }
#pragma unroll
        for (int c = 0; c < 32; c++) {
            sc[c] += __shfl_xor_sync(0xffffffffu, sc[c], 1);
            sc[c] += __shfl_xor_sync(0xffffffffu, sc[c], 2);
            int ka = kt * 32 + c;
            sc[c] = (ka <= qt) ? sc[c] * ATTN_SCALE : -1e30f;
        }
        float mt = -1e30f;
#pragma unroll
        for (int c = 0; c < 32; c++) mt = fmaxf(mt, sc[c]);
        float mnew = fmaxf(m, mt);
        float alpha = __expf(m - mnew);
        float psum = 0.f;
#pragma unroll
        for (int c = 0; c < 32; c++) { sc[c] = __expf(sc[c] - mnew); psum += sc[c]; }
        l = l * alpha + psum;
        m = mnew;
#pragma unroll
        for (int d = 0; d < 32; d++) acc[d] *= alpha;
#pragma unroll 4
        for (int c = 0; c < 32; c++) {
            float pc = sc[c];
#pragma unroll
            for (int d = 0; d < 32; d++) acc[d] = fmaf(pc, Vs[c][j * 32 + d], acc[d]);
        }
        __syncthreads();
    }
    float inv = 1.f / l;
    __half* op = out + (size_t)qt * H + h * HD + j * 32;
#pragma unroll
    for (int d = 0; d < 32; d++) op[d] = __float2half(acc[d] * inv);
}

/* ===================== fp32 W[K][N] -> fp16 [N][K] (transpose) ===================== */
__global__ void cvt_wT_kernel(const float* __restrict__ W,
                              __half* __restrict__ bh, int Kd, int Nd)
{
    __shared__ float t[32][33];
    size_t zoff = (size_t)blockIdx.z * Kd * Nd;
    W += zoff; bh += zoff;
    int n0 = blockIdx.x * 32, k0 = blockIdx.y * 32;
    int tx = threadIdx.x, ty = threadIdx.y;
#pragma unroll
    for (int r = ty; r < 32; r += 8)
        t[r][tx] = W[(size_t)(k0 + r) * Nd + n0 + tx];
    __syncthreads();
#pragma unroll
    for (int r = ty; r < 32; r += 8)
        bh[(size_t)(n0 + r) * Kd + k0 + tx] = __float2half(t[tx][r]);
}

/* ===================== fp16 tensor-core GEMM (mma.sync, single term) =====================
 * C[M,N] = A[M,K] @ W[K,N], W pre-transposed [N][K] fp16, A fp16 row-major.
 * CTA 128x128, BK=64, 3-stage cp.async pipeline. 8 warps = 4(m) x 2(n); warp 32x64.
 * Smem rows padded to 144B (conflict-free ldmatrix).
 * grouped: rows gathered via g_perm per expert (blockIdx.z). */
#define ROWB 144
#define ASTG (128 * ROWB)              /* 18432 */
#define STAGEB (2 * ASTG)              /* 36864: A then B */
#define NST 3
#define GSMEM (512 + NST * STAGEB)     /* 111104 */

__global__ __launch_bounds__(256, 1) void mma_gemm_kernel(
    const uint4* __restrict__ A4, const uint4* __restrict__ B4,
    float* __restrict__ C, const float* __restrict__ addC,
    int N, int K, int accumulate, int grouped)
{
    extern __shared__ __align__(16) char smem[];
    const int tid = threadIdx.x;
    const int wid = tid >> 5;
    const int lane = tid & 31;
    const int warp_m = wid >> 1;
    const int warp_n = wid & 1;
    const int n0 = blockIdx.x * 128;
    const int m0 = blockIdx.y * 128;

    if (grouped) {
        int cnt = g_cnt[blockIdx.z];
        if (m0 >= cnt) return;
        size_t bstride = ((size_t)N * K) >> 3;
        B4 += (size_t)blockIdx.z * bstride;
    }
    int* rows = (int*)smem;
    {
        int cnt = grouped ? g_cnt[blockIdx.z] : 0;
        int off = grouped ? g_off[blockIdx.z] : 0;
        for (int i = tid; i < 128; i += 256)
            rows[i] = grouped ? ((m0 + i < cnt) ? g_perm[off + m0 + i] : -1) : (m0 + i);
    }
    __syncthreads();

    const uint32_t sb = smem_u32(smem);
    const int K8 = K >> 3;            /* uint4 per row */
    const int nch = K >> 6;           /* chunks of 64 */

    /* load geometry: thread t -> row t>>1, 4 consecutive uint4 at (t&1)*4 */
    const int lrow = tid >> 1;
    const int cj = (tid & 1) * 4;
    int ra = rows[lrow];
    uint32_t szA = (ra >= 0) ? 16u : 0u;
    size_t ibA = (size_t)(ra >= 0 ? ra : 0) * K8 + cj;
    size_t ibB = (size_t)(n0 + lrow) * K8 + cj;
    uint32_t dof = (uint32_t)(lrow * ROWB + cj * 16);

    /* ldmatrix bases */
    uint32_t aRowOff = (uint32_t)((warp_m * 32 + (lane & 15)) * ROWB + (lane >> 4) * 16);
    int g = lane >> 3;
    uint32_t bRowOff = (uint32_t)((warp_n * 64 + (g >> 1) * 8 + (lane & 7)) * ROWB + (g & 1) * 16);

    float acc[2][8][4];
#pragma unroll
    for (int mt = 0; mt < 2; mt++)
#pragma unroll
        for (int nt = 0; nt < 8; nt++)
#pragma unroll
            for (int q = 0; q < 4; q++) acc[mt][nt][q] = 0.f;

    auto stageBase = [&](int s) { return sb + 512 + (uint32_t)s * STAGEB; };
    auto issue = [&](int c) {
        uint32_t tb = stageBase(c % NST);
        size_t ko = (size_t)c * 8;
#pragma unroll
        for (int j2 = 0; j2 < 4; j2++) {
            CP16(tb + dof + j2 * 16,        (const void*)(A4 + ibA + ko + j2), szA);
            CP16(tb + ASTG + dof + j2 * 16, (const void*)(B4 + ibB + ko + j2), 16u);
        }
    };

    /* prologue: chunks 0,1 */
    issue(0);
    asm volatile("cp.async.commit_group;" ::: "memory");
    if (nch > 1) issue(1);
    asm volatile("cp.async.commit_group;" ::: "memory");

    for (int c = 0; c < nch; c++) {
        asm volatile("cp.async.wait_group 1;" ::: "memory");
        __syncthreads();
        if (c + 2 < nch) issue(c + 2);
        asm volatile("cp.async.commit_group;" ::: "memory");

        uint32_t aB = stageBase(c % NST);
        uint32_t bB = aB + ASTG;
#pragma unroll
        for (int kk = 0; kk < 4; kk++) {
            uint32_t ah[2][4];
            ldm4(ah[0], aB + aRowOff + kk * 32);
            ldm4(ah[1], aB + aRowOff + 2304 + kk * 32);
            uint32_t bh[4][4];
#pragma unroll
            for (int p = 0; p < 4; p++)
                ldm4(bh[p], bB + bRowOff + p * 2304 + kk * 32);
#pragma unroll
            for (int mt = 0; mt < 2; mt++)
#pragma unroll
                for (int p = 0; p < 4; p++)
#pragma unroll
                    for (int hh = 0; hh < 2; hh++)
                        mma_f16(acc[mt][p * 2 + hh], ah[mt], &bh[p][hh * 2]);
        }
    }

    /* epilogue */
    int lr = lane >> 2, lc = (lane & 3) * 2;
#pragma unroll
    for (int mt = 0; mt < 2; mt++) {
        int rloc = warp_m * 32 + mt * 16 + lr;
        int grow0 = rows[rloc];
        int grow1 = rows[rloc + 8];
#pragma unroll
        for (int nt = 0; nt < 8; nt++) {
            int col = n0 + warp_n * 64 + nt * 8 + lc;
            float* a4 = acc[mt][nt];
            if (grow0 >= 0) {
                size_t cb = (size_t)grow0 * N + col;
                if (accumulate) { C[cb] += a4[0]; C[cb + 1] += a4[1]; }
                else if (addC)  { C[cb] = a4[0] + addC[cb]; C[cb + 1] = a4[1] + addC[cb + 1]; }
                else            { C[cb] = a4[0]; C[cb + 1] = a4[1]; }
            }
            if (grow1 >= 0) {
                size_t cb = (size_t)grow1 * N + col;
                if (accumulate) { C[cb] += a4[2]; C[cb + 1] += a4[3]; }
                else if (addC)  { C[cb] = a4[2] + addC[cb]; C[cb + 1] = a4[3] + addC[cb + 1]; }
                else            { C[cb] = a4[2]; C[cb + 1] = a4[3]; }
            }
        }
    }
}

/* ===================== router (fp16 xw out) ===================== */
__global__ void router_kernel(const float* __restrict__ x2, const float* __restrict__ rw,
                              int* __restrict__ topidx, __half* __restrict__ xwh)
{
    int t = blockIdx.x, tid = threadIdx.x;
    size_t base = (size_t)t * H;
    float part[E];
#pragma unroll
    for (int e = 0; e < E; e++) part[e] = 0.f;
    for (int c = tid; c < H; c += 256) {
        float xv = x2[base + c];
#pragma unroll
        for (int e = 0; e < E; e++) part[e] = fmaf(xv, rw[c * E + e], part[e]);
    }
    __shared__ float red[256][E];
#pragma unroll
    for (int e = 0; e < E; e++) red[tid][e] = part[e];
    __syncthreads();
    for (int s = 128; s > 0; s >>= 1) {
        if (tid < s)
#pragma unroll
            for (int e = 0; e < E; e++) red[tid][e] += red[tid + s][e];
        __syncthreads();
    }
    __shared__ float s_scale;
    if (tid == 0) {
        float best = red[0][0]; int bi = 0;
        for (int e = 1; e < E; e++) if (red[0][e] > best) { best = red[0][e]; bi = e; }
        topidx[t] = bi;
        s_scale = 1.f / (1.f + expf(-best));
    }
    __syncthreads();
    float scv = s_scale;
    for (int c = tid; c < H; c += 256) xwh[base + c] = __float2half(x2[base + c] * scv);
}

/* ===================== expert histogram + permutation ===================== */
__global__ void hist_kernel()
{
    __shared__ int cnt[E], off[E], run[E];
    int tid = threadIdx.x;
    if (tid < E) { cnt[tid] = 0; run[tid] = 0; }
    __syncthreads();
    for (int t = tid; t < T; t += 256) atomicAdd(&cnt[g_topidx[t]], 1);
    __syncthreads();
    if (tid == 0) {
        int o = 0;
        for (int e = 0; e < E; e++) { off[e] = o; o += cnt[e]; }
    }
    __syncthreads();
    for (int t = tid; t < T; t += 256) {
        int e = g_topidx[t];
        int p = atomicAdd(&run[e], 1);
        g_perm[off[e] + p] = t;
    }
    __syncthreads();
    if (tid < E) { g_cnt[tid] = cnt[tid]; g_off[tid] = off[tid]; }
}

/* ===================== silu(g)*u -> fp16 ===================== */
__global__ void silu_cvt_kernel(const float* __restrict__ g, const float* __restrict__ u,
                                __half* __restrict__ oh, int n)
{
    int i = blockIdx.x * 256 + threadIdx.x;
    if (i < n) {
        float gv = g[i];
        float sg = 1.f / (1.f + __expf(-gv));
        oh[i] = __float2half(gv * sg * u[i]);
    }
}

/* ===================== launch ===================== */
extern "C" void kernel_launch(void* const* d_in, const int* in_sizes, int n_in,
                              void* d_out, int out_size)
{
    (void)in_sizes; (void)n_in; (void)out_size;
    const int*   positions = (const int*)d_in[0];
    const float* hidden    = (const float*)d_in[1];
    const float* residual  = (const float*)d_in[2];
    const float* ln1w      = (const float*)d_in[3];
    const float* ln2w      = (const float*)d_in[4];
    const float* w_qkv     = (const float*)d_in[5];
    const float* w_o       = (const float*)d_in[6];
    const float* router_w  = (const float*)d_in[7];
    const float* we_gate   = (const float*)d_in[8];
    const float* we_up     = (const float*)d_in[9];
    const float* we_down   = (const float*)d_in[10];
    const float* ws_gate   = (const float*)d_in[11];
    const float* ws_up     = (const float*)d_in[12];
    const float* ws_down   = (const float*)d_in[13];

    float* out  = (float*)d_out;
    float* res2 = out + (size_t)T * H;

    float *p_res, *p_x, *p_qkv, *p_g, *p_u;
    int *p_top;
    uint4 *wq, *wo, *wsg, *wsu, *wsd, *weg, *weu, *wed, *a1, *a2;
    cudaGetSymbolAddress((void**)&p_res,  g_res);
    cudaGetSymbolAddress((void**)&p_x,    g_x);
    cudaGetSymbolAddress((void**)&p_qkv,  g_qkv);
    cudaGetSymbolAddress((void**)&p_g,    g_gbuf);
    cudaGetSymbolAddress((void**)&p_u,    g_ubuf);
    cudaGetSymbolAddress((void**)&p_top,  g_topidx);
    cudaGetSymbolAddress((void**)&wq,  b_qkv);
    cudaGetSymbolAddress((void**)&wo,  b_o);
    cudaGetSymbolAddress((void**)&wsg, b_wsg);
    cudaGetSymbolAddress((void**)&wsu, b_wsu);
    cudaGetSymbolAddress((void**)&wsd, b_wsd);
    cudaGetSymbolAddress((void**)&weg, b_weg);
    cudaGetSymbolAddress((void**)&weu, b_weu);
    cudaGetSymbolAddress((void**)&wed, b_wed);
    cudaGetSymbolAddress((void**)&a1,  g_act1);
    cudaGetSymbolAddress((void**)&a2,  g_act2);
    __half* h1 = (__half*)a1;
    __half* h2 = (__half*)a2;

    cudaFuncSetAttribute(mma_gemm_kernel, cudaFuncAttributeMaxDynamicSharedMemorySize, GSMEM);

    dim3 tb(32, 8);
    cvt_wT_kernel<<<dim3(QKVW/32, H/32, 1), tb>>>(w_qkv, (__half*)wq, H, QKVW);
    cvt_wT_kernel<<<dim3(H/32, H/32, 1), tb>>>(w_o, (__half*)wo, H, H);
    cvt_wT_kernel<<<dim3(I_DIM/32, H/32, 1), tb>>>(ws_gate, (__half*)wsg, H, I_DIM);
    cvt_wT_kernel<<<dim3(I_DIM/32, H/32, 1), tb>>>(ws_up,   (__half*)wsu, H, I_DIM);
    cvt_wT_kernel<<<dim3(H/32, I_DIM/32, 1), tb>>>(ws_down, (__half*)wsd, I_DIM, H);
    cvt_wT_kernel<<<dim3(I_DIM/32, H/32, E), tb>>>(we_gate, (__half*)weg, H, I_DIM);
    cvt_wT_kernel<<<dim3(I_DIM/32, H/32, E), tb>>>(we_up,   (__half*)weu, H, I_DIM);
    cvt_wT_kernel<<<dim3(H/32, I_DIM/32, E), tb>>>(we_down, (__half*)wed, I_DIM, H);

    /* 1. hs = hidden+residual ; res ; xh = rmsnorm (fp16 only) */
    addnorm_kernel<<<T, 256>>>(hidden, residual, ln1w, p_res, 0, h1);
    /* 2. qkv = x @ w_qkv */
    mma_gemm_kernel<<<dim3(QKVW/128, T/128, 1), 256, GSMEM>>>(a1, wq, p_qkv, 0, QKVW, H, 0, 0);
    /* 3-4. rope + attention (fp16 out into h1) */
    rope_qknorm_kernel<<<dim3(T, NH + NKV), 128>>>(p_qkv, positions);
    attn_kernel<<<dim3(T / 32, NH), 128>>>(p_qkv, h1);
    /* 5. res2 = attn @ w_o + res */
    mma_gemm_kernel<<<dim3(H/128, T/128, 1), 256, GSMEM>>>(a1, wo, res2, p_res, H, H, 0, 0);
    /* 6. x2 = rmsnorm(res2): fp32 for router + fp16 for GEMMs */
    addnorm_kernel<<<T, 256>>>(res2, 0, ln2w, 0, p_x, h1);
    /* 7-8. router (fp16 xw into h2) + grouping */
    router_kernel<<<T, 256>>>(p_x, router_w, p_top, h2);
    hist_kernel<<<1, 256>>>();
    /* 9-12. shared expert */
    mma_gemm_kernel<<<dim3(I_DIM/128, T/128, 1), 256, GSMEM>>>(a1, wsg, p_g, 0, I_DIM, H, 0, 0);
    mma_gemm_kernel<<<dim3(I_DIM/128, T/128, 1), 256, GSMEM>>>(a1, wsu, p_u, 0, I_DIM, H, 0, 0);
    silu_cvt_kernel<<<((size_t)T * I_DIM + 255) / 256, 256>>>(p_g, p_u, h1, T * I_DIM);
    mma_gemm_kernel<<<dim3(H/128, T/128, 1), 256, GSMEM>>>(a1, wsd, out, 0, H, I_DIM, 0, 0);
    /* 13-16. routed expert (top-1, grouped) */
    mma_gemm_kernel<<<dim3(I_DIM/128, T/128, E), 256, GSMEM>>>(a2, weg, p_g, 0, I_DIM, H, 0, 1);
    mma_gemm_kernel<<<dim3(I_DIM/128, T/128, E), 256, GSMEM>>>(a2, weu, p_u, 0, I_DIM, H, 0, 1);
    silu_cvt_kernel<<<((size_t)T * I_DIM + 255) / 256, 256>>>(p_g, p_u, h1, T * I_DIM);
    mma_gemm_kernel<<<dim3(H/128, T/128, E), 256, GSMEM>>>(a1, wed, out, 0, H, I_DIM, 1, 1);
}

// round 5
// speedup vs baseline: 4.0423x; 2.3378x over previous
#include <cuda_runtime.h>
#include <cuda_fp16.h>
#include <math.h>
#include <stdint.h>

#define T    2048
#define H    2048
#define NH   16
#define NKV  4
#define HD   128
#define E    8
#define I_DIM 4096
#define QKVW ((NH + 2*NKV) * HD)   /* 3072 */
#define EPSN 1e-5f
#define THETA_F 500000.0f
#define ATTN_SCALE 0.08838834764831845f

/* ===================== scratch (device globals) ===================== */
__device__ float g_res [T*H];
__device__ float g_x   [T*H];
__device__ float g_qkv [T*QKVW];
__device__ float g_gbuf[(size_t)T*I_DIM];
__device__ float g_ubuf[(size_t)T*I_DIM];
__device__ int   g_topidx[T];
__device__ int   g_perm[T];
__device__ int   g_cnt[E];
__device__ int   g_off[E];
/* fp16 activations */
__device__ uint4 g_act1[(size_t)T*I_DIM/8];   /* x / attn / x2 / silu-g */
__device__ uint4 g_act2[(size_t)T*H/8];       /* xw (routed-expert input) */

/* ===================== small PTX wrappers ===================== */
__device__ __forceinline__ uint32_t smem_u32(const void* p) {
    uint32_t a;
    asm("{ .reg .u64 t; cvta.to.shared.u64 t, %1; cvt.u32.u64 %0, t; }" : "=r"(a) : "l"(p));
    return a;
}
__device__ __forceinline__ void ldm4(uint32_t* r, uint32_t addr) {
    asm volatile("ldmatrix.sync.aligned.m8n8.x4.shared.b16 {%0,%1,%2,%3}, [%4];"
        : "=r"(r[0]), "=r"(r[1]), "=r"(r[2]), "=r"(r[3]) : "r"(addr));
}
__device__ __forceinline__ void ldm4t(uint32_t* r, uint32_t addr) {
    asm volatile("ldmatrix.sync.aligned.m8n8.x4.trans.shared.b16 {%0,%1,%2,%3}, [%4];"
        : "=r"(r[0]), "=r"(r[1]), "=r"(r[2]), "=r"(r[3]) : "r"(addr));
}
__device__ __forceinline__ void mma_f16(float* c, const uint32_t* a, const uint32_t* b) {
    asm volatile(
        "mma.sync.aligned.m16n8k16.row.col.f32.f16.f16.f32 "
        "{%0,%1,%2,%3}, {%4,%5,%6,%7}, {%8,%9}, {%0,%1,%2,%3};"
        : "+f"(c[0]), "+f"(c[1]), "+f"(c[2]), "+f"(c[3])
        : "r"(a[0]), "r"(a[1]), "r"(a[2]), "r"(a[3]), "r"(b[0]), "r"(b[1]));
}
#define CP16(dst, src, sz) asm volatile("cp.async.cg.shared.global [%0], [%1], 16, %2;" :: "r"(dst), "l"(src), "r"(sz) : "memory")
#define STS128(addr, v) asm volatile("st.shared.v4.b32 [%0], {%1,%2,%3,%4};" :: "r"(addr), "r"((v).x), "r"((v).y), "r"((v).z), "r"((v).w) : "memory")

__device__ __forceinline__ uint4 pack8h(float4 a, float4 b) {
    __half2 h0 = __floats2half2_rn(a.x, a.y);
    __half2 h1 = __floats2half2_rn(a.z, a.w);
    __half2 h2 = __floats2half2_rn(b.x, b.y);
    __half2 h3 = __floats2half2_rn(b.z, b.w);
    uint4 r;
    r.x = *(uint32_t*)&h0; r.y = *(uint32_t*)&h1;
    r.z = *(uint32_t*)&h2; r.w = *(uint32_t*)&h3;
    return r;
}

/* ===================== add + rmsnorm (fp32 opt + fp16 out) ===================== */
__global__ void addnorm_kernel(const float* __restrict__ a, const float* __restrict__ b,
                               const float* __restrict__ w, float* __restrict__ res,
                               float* __restrict__ xout, __half* __restrict__ xh)
{
    int t = blockIdx.x;
    int tid = threadIdx.x;
    const int PER = H / 256;
    size_t base = (size_t)t * H;
    float v[PER];
    float ss = 0.f;
#pragma unroll
    for (int u = 0; u < PER; u++) {
        int c = tid + u * 256;
        float val = a[base + c];
        if (b) val += b[base + c];
        v[u] = val;
        if (res) res[base + c] = val;
        ss += val * val;
    }
    __shared__ float red[256];
    red[tid] = ss;
    __syncthreads();
    for (int s = 128; s > 0; s >>= 1) {
        if (tid < s) red[tid] += red[tid + s];
        __syncthreads();
    }
    float scale = rsqrtf(red[0] / (float)H + EPSN);
#pragma unroll
    for (int u = 0; u < PER; u++) {
        int c = tid + u * 256;
        float o = v[u] * scale * w[c];
        if (xout) xout[base + c] = o;
        xh[base + c] = __float2half(o);
    }
}

/* ===================== rope + q/k rmsnorm ===================== */
__global__ void rope_qknorm_kernel(float* __restrict__ qkv, const int* __restrict__ positions)
{
    int t  = blockIdx.x;
    int hh = blockIdx.y;
    int col0 = (hh < NH) ? hh * HD : (NH * HD + (hh - NH) * HD);
    float* p = qkv + (size_t)t * QKVW + col0;
    int d = threadIdx.x;
    float pos = (float)positions[t];
    int i = (d < 64) ? d : d - 64;
    float invf = powf(THETA_F, -(float)i / 64.f);
    float ang = pos * invf;
    float c = cosf(ang), s = sinf(ang);
    float x1 = p[i], x2 = p[i + 64];
    float val = (d < 64) ? (x1 * c - x2 * s) : (x2 * c + x1 * s);

    __shared__ float red[128];
    red[d] = val * val;
    __syncthreads();
    for (int st = 64; st > 0; st >>= 1) {
        if (d < st) red[d] += red[d + st];
        __syncthreads();
    }
    float scale = rsqrtf(red[0] / (float)HD + EPSN);
    p[d] = val * scale;
}

/* ===================== flash attention (causal, GQA), fp16 out =====================
 * conflict-free: per-lane float4 slot rotation slot=(i+2j)&7; q & acc stored rotated. */
__global__ void attn_kernel(const float* __restrict__ qkv, __half* __restrict__ out)
{
    int qb = blockIdx.x;
    int h  = blockIdx.y;
    int tid = threadIdx.x;
    int r = tid >> 2;
    int j = tid & 3;
    int qt = qb * 32 + r;
    int kvh = h >> 2;

    const float4* qkv4 = (const float4*)qkv;
    const float4* qptr4 = qkv4 + (((size_t)qt * QKVW + h * HD) >> 2) + j * 8;
    float4 q4[8];
#pragma unroll
    for (int i = 0; i < 8; i++) q4[i] = qptr4[(i + 2 * j) & 7];

    __shared__ float4 Ks4[32][32];
    __shared__ float4 Vs4[32][32];

    float m = -1e30f, l = 0.f;
    float4 acc4[8];
#pragma unroll
    for (int i = 0; i < 8; i++) acc4[i] = make_float4(0.f, 0.f, 0.f, 0.f);

    const int kOff = (NH * HD) >> 2;
    const int vOff = ((NH + NKV) * HD) >> 2;

    for (int kt = 0; kt <= qb; kt++) {
#pragma unroll
        for (int li = tid; li < 32 * 32; li += 128) {
            int row = li >> 5, u = li & 31;
            size_t gb = (((size_t)(kt * 32 + row) * QKVW + kvh * HD) >> 2) + u;
            Ks4[row][u] = qkv4[gb + kOff];
            Vs4[row][u] = qkv4[gb + vOff];
        }
        __syncthreads();

        float sc[32];
#pragma unroll 4
        for (int c = 0; c < 32; c++) {
            float a4 = 0.f;
#pragma unroll
            for (int i = 0; i < 8; i++) {
                int u = j * 8 + ((i + 2 * j) & 7);
                float4 kv = Ks4[c][u];
                float4 qq = q4[i];
                a4 = fmaf(qq.x, kv.x, a4);
                a4 = fmaf(qq.y, kv.y, a4);
                a4 = fmaf(qq.z, kv.z, a4);
                a4 = fmaf(qq.w, kv.w, a4);
            }
            sc[c] = a4;
        }
#pragma unroll
        for (int c = 0; c < 32; c++) {
            sc[c] += __shfl_xor_sync(0xffffffffu, sc[c], 1);
            sc[c] += __shfl_xor_sync(0xffffffffu, sc[c], 2);
            int ka = kt * 32 + c;
            sc[c] = (ka <= qt) ? sc[c] * ATTN_SCALE : -1e30f;
        }
        float mt = -1e30f;
#pragma unroll
        for (int c = 0; c < 32; c++) mt = fmaxf(mt, sc[c]);
        float mnew = fmaxf(m, mt);
        float alpha = __expf(m - mnew);
        float psum = 0.f;
#pragma unroll
        for (int c = 0; c < 32; c++) { sc[c] = __expf(sc[c] - mnew); psum += sc[c]; }
        l = l * alpha + psum;
        m = mnew;
#pragma unroll
        for (int i = 0; i < 8; i++) {
            acc4[i].x *= alpha; acc4[i].y *= alpha;
            acc4[i].z *= alpha; acc4[i].w *= alpha;
        }
#pragma unroll 4
        for (int c = 0; c < 32; c++) {
            float pc = sc[c];
#pragma unroll
            for (int i = 0; i < 8; i++) {
                int u = j * 8 + ((i + 2 * j) & 7);
                float4 vv = Vs4[c][u];
                acc4[i].x = fmaf(pc, vv.x, acc4[i].x);
                acc4[i].y = fmaf(pc, vv.y, acc4[i].y);
                acc4[i].z = fmaf(pc, vv.z, acc4[i].z);
                acc4[i].w = fmaf(pc, vv.w, acc4[i].w);
            }
        }
        __syncthreads();
    }
    float inv = 1.f / l;
    __half2* op2 = (__half2*)(out + (size_t)qt * H + h * HD + j * 32);
#pragma unroll
    for (int i = 0; i < 8; i++) {
        int slot = (i + 2 * j) & 7;
        op2[slot * 2]     = __floats2half2_rn(acc4[i].x * inv, acc4[i].y * inv);
        op2[slot * 2 + 1] = __floats2half2_rn(acc4[i].z * inv, acc4[i].w * inv);
    }
}

/* ===================== fp16 tensor-core GEMM, direct fp32-W load =====================
 * C[M,N] = A[M,K] @ W[K,N].  A fp16 [M][K] via cp.async (3 stages).
 * W fp32 [K][N] loaded with LDG.128, converted to fp16 in-register, STS (2 stages),
 * B fragments via ldmatrix.trans. CTA 128x128, BK=64, 8 warps (4m x 2n), warp 32x64. */
#define ROWA 144
#define ASTG (128 * ROWA)              /* 18432 */
#define NSA  3
#define ROWB2 272
#define BSTG (64 * ROWB2)              /* 17408 */
#define GSMEM (512 + NSA * ASTG + 2 * BSTG)   /* 90624 */

__global__ __launch_bounds__(256, 1) void mma_gemm_kernel(
    const uint4* __restrict__ A4, const float4* __restrict__ Wf,
    float* __restrict__ C, const float* __restrict__ addC,
    int N, int K, int accumulate, int grouped)
{
    extern __shared__ __align__(16) char smem[];
    const int tid = threadIdx.x;
    const int wid = tid >> 5;
    const int lane = tid & 31;
    const int warp_m = wid >> 1;
    const int warp_n = wid & 1;
    const int n0 = blockIdx.x * 128;
    const int m0 = blockIdx.y * 128;
    const int N4 = N >> 2;

    if (grouped) {
        int cnt = g_cnt[blockIdx.z];
        if (m0 >= cnt) return;
        Wf += (size_t)blockIdx.z * K * N4;
    }
    int* rows = (int*)smem;
    {
        int cnt = grouped ? g_cnt[blockIdx.z] : 0;
        int off = grouped ? g_off[blockIdx.z] : 0;
        for (int i = tid; i < 128; i += 256)
            rows[i] = grouped ? ((m0 + i < cnt) ? g_perm[off + m0 + i] : -1) : (m0 + i);
    }
    __syncthreads();

    const uint32_t sb = smem_u32(smem);
    const uint32_t aBase = sb + 512;
    const uint32_t bBase = aBase + NSA * ASTG;
    const int K8 = K >> 3;            /* uint4 per A row */
    const int nch = K >> 6;           /* K chunks of 64 */

    /* A load geometry: thread -> row tid>>1, 4 consecutive uint4 at (tid&1)*4 */
    const int lrow = tid >> 1;
    const int cj = (tid & 1) * 4;
    int ra = rows[lrow];
    uint32_t szA = (ra >= 0) ? 16u : 0u;
    size_t ibA = (size_t)(ra >= 0 ? ra : 0) * K8 + cj;
    uint32_t dofA = (uint32_t)(lrow * ROWA + cj * 16);

    /* B load geometry: thread -> k-row tid>>2, quarter bq=tid&3.
     * float4 pairs {2bq+8j2, 2bq+8j2+1}, j2=0..3 -> 8 float4 = 32 floats. */
    const int brow = tid >> 2;
    const int bq = tid & 3;
    const float4* wp0 = Wf + (size_t)brow * N4 + (n0 >> 2) + 2 * bq;
    const size_t wchunk = (size_t)64 * N4;     /* advance 64 k-rows */
    uint32_t bsts = (uint32_t)(brow * ROWB2 + bq * 16);

    /* ldmatrix bases */
    uint32_t aRowOff = (uint32_t)((warp_m * 32 + (lane & 15)) * ROWA + (lane >> 4) * 16);
    int g = lane >> 3;
    /* B (trans): k-row = (g&1)*8 + (lane&7), n-off = warp_n*64 + p*16 + (g>>1)*8 */
    uint32_t bRowOff = (uint32_t)(((g & 1) * 8 + (lane & 7)) * ROWB2 +
                                  (warp_n * 64 + (g >> 1) * 8) * 2);

    float acc[2][8][4];
#pragma unroll
    for (int mt = 0; mt < 2; mt++)
#pragma unroll
        for (int nt = 0; nt < 8; nt++)
#pragma unroll
            for (int q = 0; q < 4; q++) acc[mt][nt][q] = 0.f;

    auto issueA = [&](int c) {
        uint32_t tb = aBase + (uint32_t)(c % NSA) * ASTG;
        size_t ko = (size_t)c * 8;
#pragma unroll
        for (int j2 = 0; j2 < 4; j2++)
            CP16(tb + dofA + j2 * 16, (const void*)(A4 + ibA + ko + j2), szA);
    };

    float4 br[8];
    auto ldgB = [&](int c) {
        const float4* wp = wp0 + (size_t)c * wchunk;
#pragma unroll
        for (int j2 = 0; j2 < 4; j2++) {
            br[2 * j2]     = wp[8 * j2];
            br[2 * j2 + 1] = wp[8 * j2 + 1];
        }
    };
    auto stsB = [&](int s) {
        uint32_t tb = bBase + (uint32_t)s * BSTG + bsts;
#pragma unroll
        for (int j2 = 0; j2 < 4; j2++) {
            uint4 pk = pack8h(br[2 * j2], br[2 * j2 + 1]);
            STS128(tb + j2 * 64, pk);
        }
    };

    /* prologue */
    ldgB(0);
    issueA(0);
    asm volatile("cp.async.commit_group;" ::: "memory");
    if (nch > 1) issueA(1);
    asm volatile("cp.async.commit_group;" ::: "memory");

    for (int c = 0; c < nch; c++) {
        stsB(c & 1);
        asm volatile("cp.async.wait_group 1;" ::: "memory");
        __syncthreads();
        if (c + 2 < nch) issueA(c + 2);
        asm volatile("cp.async.commit_group;" ::: "memory");
        if (c + 1 < nch) ldgB(c + 1);

        uint32_t aB = aBase + (uint32_t)(c % NSA) * ASTG;
        uint32_t bB = bBase + (uint32_t)(c & 1) * BSTG;
#pragma unroll
        for (int kk = 0; kk < 4; kk++) {
            uint32_t ah[2][4];
            ldm4(ah[0], aB + aRowOff + kk * 32);
            ldm4(ah[1], aB + aRowOff + 2304 + kk * 32);
            uint32_t bh[4][4];
#pragma unroll
            for (int p = 0; p < 4; p++)
                ldm4t(bh[p], bB + bRowOff + kk * (16 * ROWB2) + p * 32);
#pragma unroll
            for (int mt = 0; mt < 2; mt++)
#pragma unroll
                for (int p = 0; p < 4; p++)
#pragma unroll
                    for (int hh = 0; hh < 2; hh++)
                        mma_f16(acc[mt][p * 2 + hh], ah[mt], &bh[p][hh * 2]);
        }
    }

    /* epilogue */
    int lr = lane >> 2, lc = (lane & 3) * 2;
#pragma unroll
    for (int mt = 0; mt < 2; mt++) {
        int rloc = warp_m * 32 + mt * 16 + lr;
        int grow0 = rows[rloc];
        int grow1 = rows[rloc + 8];
#pragma unroll
        for (int nt = 0; nt < 8; nt++) {
            int col = n0 + warp_n * 64 + nt * 8 + lc;
            float* a4 = acc[mt][nt];
            if (grow0 >= 0) {
                size_t cb = (size_t)grow0 * N + col;
                if (accumulate) { C[cb] += a4[0]; C[cb + 1] += a4[1]; }
                else if (addC)  { C[cb] = a4[0] + addC[cb]; C[cb + 1] = a4[1] + addC[cb + 1]; }
                else            { C[cb] = a4[0]; C[cb + 1] = a4[1]; }
            }
            if (grow1 >= 0) {
                size_t cb = (size_t)grow1 * N + col;
                if (accumulate) { C[cb] += a4[2]; C[cb + 1] += a4[3]; }
                else if (addC)  { C[cb] = a4[2] + addC[cb]; C[cb + 1] = a4[3] + addC[cb + 1]; }
                else            { C[cb] = a4[2]; C[cb + 1] = a4[3]; }
            }
        }
    }
}

/* ===================== router (fp16 xw out) ===================== */
__global__ void router_kernel(const float* __restrict__ x2, const float* __restrict__ rw,
                              int* __restrict__ topidx, __half* __restrict__ xwh)
{
    int t = blockIdx.x, tid = threadIdx.x;
    size_t base = (size_t)t * H;
    float part[E];
#pragma unroll
    for (int e = 0; e < E; e++) part[e] = 0.f;
    for (int c = tid; c < H; c += 256) {
        float xv = x2[base + c];
#pragma unroll
        for (int e = 0; e < E; e++) part[e] = fmaf(xv, rw[c * E + e], part[e]);
    }
    __shared__ float red[256][E];
#pragma unroll
    for (int e = 0; e < E; e++) red[tid][e] = part[e];
    __syncthreads();
    for (int s = 128; s > 0; s >>= 1) {
        if (tid < s)
#pragma unroll
            for (int e = 0; e < E; e++) red[tid][e] += red[tid + s][e];
        __syncthreads();
    }
    __shared__ float s_scale;
    if (tid == 0) {
        float best = red[0][0]; int bi = 0;
        for (int e = 1; e < E; e++) if (red[0][e] > best) { best = red[0][e]; bi = e; }
        topidx[t] = bi;
        s_scale = 1.f / (1.f + expf(-best));
    }
    __syncthreads();
    float scv = s_scale;
    for (int c = tid; c < H; c += 256) xwh[base + c] = __float2half(x2[base + c] * scv);
}

/* ===================== expert histogram + permutation ===================== */
__global__ void hist_kernel()
{
    __shared__ int cnt[E], off[E], run[E];
    int tid = threadIdx.x;
    if (tid < E) { cnt[tid] = 0; run[tid] = 0; }
    __syncthreads();
    for (int t = tid; t < T; t += 256) atomicAdd(&cnt[g_topidx[t]], 1);
    __syncthreads();
    if (tid == 0) {
        int o = 0;
        for (int e = 0; e < E; e++) { off[e] = o; o += cnt[e]; }
    }
    __syncthreads();
    for (int t = tid; t < T; t += 256) {
        int e = g_topidx[t];
        int p = atomicAdd(&run[e], 1);
        g_perm[off[e] + p] = t;
    }
    __syncthreads();
    if (tid < E) { g_cnt[tid] = cnt[tid]; g_off[tid] = off[tid]; }
}

/* ===================== silu(g)*u -> fp16 ===================== */
__global__ void silu_cvt_kernel(const float* __restrict__ g, const float* __restrict__ u,
                                __half* __restrict__ oh, int n)
{
    int i = blockIdx.x * 256 + threadIdx.x;
    if (i < n) {
        float gv = g[i];
        float sg = 1.f / (1.f + __expf(-gv));
        oh[i] = __float2half(gv * sg * u[i]);
    }
}

/* ===================== launch ===================== */
extern "C" void kernel_launch(void* const* d_in, const int* in_sizes, int n_in,
                              void* d_out, int out_size)
{
    (void)in_sizes; (void)n_in; (void)out_size;
    const int*   positions = (const int*)d_in[0];
    const float* hidden    = (const float*)d_in[1];
    const float* residual  = (const float*)d_in[2];
    const float* ln1w      = (const float*)d_in[3];
    const float* ln2w      = (const float*)d_in[4];
    const float* w_qkv     = (const float*)d_in[5];
    const float* w_o       = (const float*)d_in[6];
    const float* router_w  = (const float*)d_in[7];
    const float* we_gate   = (const float*)d_in[8];
    const float* we_up     = (const float*)d_in[9];
    const float* we_down   = (const float*)d_in[10];
    const float* ws_gate   = (const float*)d_in[11];
    const float* ws_up     = (const float*)d_in[12];
    const float* ws_down   = (const float*)d_in[13];

    float* out  = (float*)d_out;
    float* res2 = out + (size_t)T * H;

    float *p_res, *p_x, *p_qkv, *p_g, *p_u;
    int *p_top;
    uint4 *a1, *a2;
    cudaGetSymbolAddress((void**)&p_res,  g_res);
    cudaGetSymbolAddress((void**)&p_x,    g_x);
    cudaGetSymbolAddress((void**)&p_qkv,  g_qkv);
    cudaGetSymbolAddress((void**)&p_g,    g_gbuf);
    cudaGetSymbolAddress((void**)&p_u,    g_ubuf);
    cudaGetSymbolAddress((void**)&p_top,  g_topidx);
    cudaGetSymbolAddress((void**)&a1,  g_act1);
    cudaGetSymbolAddress((void**)&a2,  g_act2);
    __half* h1 = (__half*)a1;
    __half* h2 = (__half*)a2;

    cudaFuncSetAttribute(mma_gemm_kernel, cudaFuncAttributeMaxDynamicSharedMemorySize, GSMEM);

    /* 1. hs = hidden+residual ; res ; xh = rmsnorm (fp16) */
    addnorm_kernel<<<T, 256>>>(hidden, residual, ln1w, p_res, 0, h1);
    /* 2. qkv = x @ w_qkv */
    mma_gemm_kernel<<<dim3(QKVW/128, T/128, 1), 256, GSMEM>>>(a1, (const float4*)w_qkv, p_qkv, 0, QKVW, H, 0, 0);
    /* 3-4. rope + attention (fp16 out into h1) */
    rope_qknorm_kernel<<<dim3(T, NH + NKV), 128>>>(p_qkv, positions);
    attn_kernel<<<dim3(T / 32, NH), 128>>>(p_qkv, h1);
    /* 5. res2 = attn @ w_o + res */
    mma_gemm_kernel<<<dim3(H/128, T/128, 1), 256, GSMEM>>>(a1, (const float4*)w_o, res2, p_res, H, H, 0, 0);
    /* 6. x2 = rmsnorm(res2): fp32 for router + fp16 for GEMMs */
    addnorm_kernel<<<T, 256>>>(res2, 0, ln2w, 0, p_x, h1);
    /* 7-8. router (fp16 xw into h2) + grouping */
    router_kernel<<<T, 256>>>(p_x, router_w, p_top, h2);
    hist_kernel<<<1, 256>>>();
    /* 9-12. shared expert */
    mma_gemm_kernel<<<dim3(I_DIM/128, T/128, 1), 256, GSMEM>>>(a1, (const float4*)ws_gate, p_g, 0, I_DIM, H, 0, 0);
    mma_gemm_kernel<<<dim3(I_DIM/128, T/128, 1), 256, GSMEM>>>(a1, (const float4*)ws_up,   p_u, 0, I_DIM, H, 0, 0);
    silu_cvt_kernel<<<((size_t)T * I_DIM + 255) / 256, 256>>>(p_g, p_u, h1, T * I_DIM);
    mma_gemm_kernel<<<dim3(H/128, T/128, 1), 256, GSMEM>>>(a1, (const float4*)ws_down, out, 0, H, I_DIM, 0, 0);
    /* 13-16. routed expert (top-1, grouped) */
    mma_gemm_kernel<<<dim3(I_DIM/128, T/128, E), 256, GSMEM>>>(a2, (const float4*)we_gate, p_g, 0, I_DIM, H, 0, 1);
    mma_gemm_kernel<<<dim3(I_DIM/128, T/128, E), 256, GSMEM>>>(a2, (const float4*)we_up,   p_u, 0, I_DIM, H, 0, 1);
    silu_cvt_kernel<<<((size_t)T * I_DIM + 255) / 256, 256>>>(p_g, p_u, h1, T * I_DIM);
    mma_gemm_kernel<<<dim3(H/128, T/128, E), 256, GSMEM>>>(a1, (const float4*)we_down, out, 0, H, I_DIM, 1, 1);
}

// round 6
// speedup vs baseline: 5.0609x; 1.2520x over previous
#include <cuda_runtime.h>
#include <cuda_fp16.h>
#include <math.h>
#include <stdint.h>

#define T    2048
#define H    2048
#define NH   16
#define NKV  4
#define HD   128
#define E    8
#define I_DIM 4096
#define QKVW ((NH + 2*NKV) * HD)   /* 3072 */
#define EPSN 1e-5f
#define THETA_F 500000.0f
#define ATTN_SCALE 0.08838834764831845f

/* ===================== scratch (device globals) ===================== */
__device__ float g_res [T*H];
__device__ float g_x   [T*H];
__device__ float g_qkv [T*QKVW];
__device__ int   g_topidx[T];
__device__ int   g_perm[T];
__device__ int   g_cnt[E];
__device__ int   g_off[E];
/* fp16 buffers */
__device__ uint4 g_act1[(size_t)T*I_DIM/8];   /* x / attn-out / x2 / silu-out */
__device__ uint4 g_act2[(size_t)T*H/8];       /* xw */
__device__ uint4 g_gh[(size_t)T*I_DIM/8];     /* gate fp16 */
__device__ uint4 g_uh[(size_t)T*I_DIM/8];     /* up fp16 */
__device__ uint4 g_qh[(size_t)T*NH*HD/8];     /* q fp16 (scaled) [t][h][d] */
__device__ uint4 g_kh[(size_t)NKV*T*HD/8];    /* k fp16 [kvh][t][d] */
__device__ uint4 g_vh[(size_t)NKV*T*HD/8];    /* v fp16 [kvh][t][d] */

/* ===================== small PTX wrappers ===================== */
__device__ __forceinline__ uint32_t smem_u32(const void* p) {
    uint32_t a;
    asm("{ .reg .u64 t; cvta.to.shared.u64 t, %1; cvt.u32.u64 %0, t; }" : "=r"(a) : "l"(p));
    return a;
}
__device__ __forceinline__ void ldm4(uint32_t* r, uint32_t addr) {
    asm volatile("ldmatrix.sync.aligned.m8n8.x4.shared.b16 {%0,%1,%2,%3}, [%4];"
        : "=r"(r[0]), "=r"(r[1]), "=r"(r[2]), "=r"(r[3]) : "r"(addr));
}
__device__ __forceinline__ void ldm4t(uint32_t* r, uint32_t addr) {
    asm volatile("ldmatrix.sync.aligned.m8n8.x4.trans.shared.b16 {%0,%1,%2,%3}, [%4];"
        : "=r"(r[0]), "=r"(r[1]), "=r"(r[2]), "=r"(r[3]) : "r"(addr));
}
__device__ __forceinline__ void mma_f16(float* c, const uint32_t* a, const uint32_t* b) {
    asm volatile(
        "mma.sync.aligned.m16n8k16.row.col.f32.f16.f16.f32 "
        "{%0,%1,%2,%3}, {%4,%5,%6,%7}, {%8,%9}, {%0,%1,%2,%3};"
        : "+f"(c[0]), "+f"(c[1]), "+f"(c[2]), "+f"(c[3])
        : "r"(a[0]), "r"(a[1]), "r"(a[2]), "r"(a[3]), "r"(b[0]), "r"(b[1]));
}
#define CP16(dst, src, sz) asm volatile("cp.async.cg.shared.global [%0], [%1], 16, %2;" :: "r"(dst), "l"(src), "r"(sz) : "memory")
#define STS128(addr, v) asm volatile("st.shared.v4.b32 [%0], {%1,%2,%3,%4};" :: "r"(addr), "r"((v).x), "r"((v).y), "r"((v).z), "r"((v).w) : "memory")

__device__ __forceinline__ uint4 pack8h(float4 a, float4 b) {
    __half2 h0 = __floats2half2_rn(a.x, a.y);
    __half2 h1 = __floats2half2_rn(a.z, a.w);
    __half2 h2 = __floats2half2_rn(b.x, b.y);
    __half2 h3 = __floats2half2_rn(b.z, b.w);
    uint4 r;
    r.x = *(uint32_t*)&h0; r.y = *(uint32_t*)&h1;
    r.z = *(uint32_t*)&h2; r.w = *(uint32_t*)&h3;
    return r;
}

/* ===================== add + rmsnorm ===================== */
__global__ void addnorm_kernel(const float* __restrict__ a, const float* __restrict__ b,
                               const float* __restrict__ w, float* __restrict__ res,
                               float* __restrict__ xout, __half* __restrict__ xh)
{
    int t = blockIdx.x;
    int tid = threadIdx.x;
    const int PER = H / 256;
    size_t base = (size_t)t * H;
    float v[PER];
    float ss = 0.f;
#pragma unroll
    for (int u = 0; u < PER; u++) {
        int c = tid + u * 256;
        float val = a[base + c];
        if (b) val += b[base + c];
        v[u] = val;
        if (res) res[base + c] = val;
        ss += val * val;
    }
    __shared__ float red[256];
    red[tid] = ss;
    __syncthreads();
    for (int s = 128; s > 0; s >>= 1) {
        if (tid < s) red[tid] += red[tid + s];
        __syncthreads();
    }
    float scale = rsqrtf(red[0] / (float)H + EPSN);
#pragma unroll
    for (int u = 0; u < PER; u++) {
        int c = tid + u * 256;
        float o = v[u] * scale * w[c];
        if (xout) xout[base + c] = o;
        xh[base + c] = __float2half(o);
    }
}

/* ===================== rope + q/k rmsnorm + fp16 conversion ===================== */
__global__ void rope_cvt_kernel(const float* __restrict__ qkv, const int* __restrict__ positions,
                                __half* __restrict__ qh, __half* __restrict__ kh,
                                __half* __restrict__ vh)
{
    int t  = blockIdx.x;
    int hh = blockIdx.y;   /* 0..NH+2NKV-1 */
    int d  = threadIdx.x;
    const float* p = qkv + (size_t)t * QKVW + hh * HD;
    if (hh >= NH + NKV) {
        int kvh = hh - NH - NKV;
        vh[((size_t)kvh * T + t) * HD + d] = __float2half(p[d]);
        return;
    }
    float pos = (float)positions[t];
    int i = (d < 64) ? d : d - 64;
    float invf = powf(THETA_F, -(float)i / 64.f);
    float ang = pos * invf;
    float c = cosf(ang), s = sinf(ang);
    float x1 = p[i], x2 = p[i + 64];
    float val = (d < 64) ? (x1 * c - x2 * s) : (x2 * c + x1 * s);

    __shared__ float red[128];
    red[d] = val * val;
    __syncthreads();
    for (int st = 64; st > 0; st >>= 1) {
        if (d < st) red[d] += red[d + st];
        __syncthreads();
    }
    float scale = rsqrtf(red[0] / (float)HD + EPSN);
    val *= scale;
    if (hh < NH) qh[((size_t)t * NH + hh) * HD + d] = __float2half(val * ATTN_SCALE);
    else         kh[((size_t)(hh - NH) * T + t) * HD + d] = __float2half(val);
}

/* ===================== fp16 mma flash attention (causal, GQA) =====================
 * 64 queries x 64 keys tiles, 4 warps (16 q-rows each), HD=128.
 * K/V fp16 from global, cp.async double-buffered. fp32 softmax. */
#define AROW 272                 /* 128 halves + 8 pad, bytes */
#define ATILE (64 * AROW)        /* 17408 */
#define ASMEM (5 * ATILE)        /* Q + 2K + 2V = 87040 */

__global__ __launch_bounds__(128) void attn_mma_kernel(
    const __half* __restrict__ qh, const __half* __restrict__ kh,
    const __half* __restrict__ vh, __half* __restrict__ out)
{
    extern __shared__ __align__(16) char smem[];
    const int qb  = blockIdx.x;
    const int h   = blockIdx.y;
    const int kvh = h >> 2;
    const int tid = threadIdx.x;
    const int wq  = tid >> 5;
    const int lane = tid & 31;
    const int q0 = qb * 64;
    const int g2 = lane >> 3;

    uint32_t sb = smem_u32(smem);
    const uint32_t sK0 = sb + ATILE;
    const uint32_t sV0 = sb + 3 * ATILE;

    /* Q tile (fp16 gmem -> smem) */
    {
        const uint4* qg = (const uint4*)(qh + ((size_t)q0 * NH + h) * HD);
#pragma unroll
        for (int i = 0; i < 8; i++) {
            int idx = tid + i * 128;
            int row = idx >> 4, c = idx & 15;
            uint4 v = qg[(size_t)row * (NH * HD / 8) + c];
            *(uint4*)(smem + row * AROW + c * 16) = v;
        }
    }

    const char* kg = (const char*)(kh + (size_t)kvh * T * HD);
    const char* vg = (const char*)(vh + (size_t)kvh * T * HD);
    auto loadKV = [&](int kt, int s) {
        uint32_t dk = sK0 + (uint32_t)s * ATILE;
        uint32_t dv = sV0 + (uint32_t)s * ATILE;
        const char* kgt = kg + (size_t)kt * 64 * 256;
        const char* vgt = vg + (size_t)kt * 64 * 256;
#pragma unroll
        for (int i = 0; i < 8; i++) {
            int idx = tid + i * 128;
            int row = idx >> 4, c = idx & 15;
            uint32_t o = row * AROW + c * 16;
            int go = row * 256 + c * 16;
            CP16(dk + o, kgt + go, 16);
            CP16(dv + o, vgt + go, 16);
        }
    };

    loadKV(0, 0);
    asm volatile("cp.async.commit_group;" ::: "memory");
    __syncthreads();   /* Q stores visible */

    /* Q fragments held for the whole loop */
    uint32_t aq[8][4];
    {
        uint32_t aOff = sb + (wq * 16 + (lane & 15)) * AROW + (lane >> 4) * 16;
#pragma unroll
        for (int kk = 0; kk < 8; kk++) ldm4(aq[kk], aOff + kk * 32);
    }

    float m0 = -1e30f, m1 = -1e30f, l0 = 0.f, l1 = 0.f;
    float o[16][4];
#pragma unroll
    for (int nt = 0; nt < 16; nt++)
#pragma unroll
        for (int q = 0; q < 4; q++) o[nt][q] = 0.f;

    const int ktmax = qb;
    for (int kt = 0; kt <= ktmax; kt++) {
        if (kt + 1 <= ktmax) loadKV(kt + 1, (kt + 1) & 1);
        asm volatile("cp.async.commit_group;" ::: "memory");
        if (kt == ktmax) asm volatile("cp.async.wait_group 0;" ::: "memory");
        else             asm volatile("cp.async.wait_group 1;" ::: "memory");
        __syncthreads();

        uint32_t kB = sK0 + (uint32_t)(kt & 1) * ATILE;
        uint32_t vB = sV0 + (uint32_t)(kt & 1) * ATILE;

        /* scores S = Q @ K^T */
        float sc[8][4];
#pragma unroll
        for (int nt = 0; nt < 8; nt++)
#pragma unroll
            for (int q = 0; q < 4; q++) sc[nt][q] = 0.f;

        uint32_t bOffK = kB + ((g2 >> 1) * 8 + (lane & 7)) * AROW + (g2 & 1) * 16;
#pragma unroll
        for (int kk = 0; kk < 8; kk++) {
            uint32_t kb[4][4];
#pragma unroll
            for (int p = 0; p < 4; p++)
                ldm4(kb[p], bOffK + p * (16 * AROW) + kk * 32);
#pragma unroll
            for (int p = 0; p < 4; p++) {
                mma_f16(sc[2 * p],     aq[kk], &kb[p][0]);
                mma_f16(sc[2 * p + 1], aq[kk], &kb[p][2]);
            }
        }

        /* causal mask (diagonal tile only) */
        int row0 = q0 + wq * 16 + (lane >> 2);
        if (kt == ktmax) {
            int colb = kt * 64 + 2 * (lane & 3);
#pragma unroll
            for (int nt = 0; nt < 8; nt++) {
                int c0 = colb + nt * 8;
                if (c0 > row0)         sc[nt][0] = -1e30f;
                if (c0 + 1 > row0)     sc[nt][1] = -1e30f;
                if (c0 > row0 + 8)     sc[nt][2] = -1e30f;
                if (c0 + 1 > row0 + 8) sc[nt][3] = -1e30f;
            }
        }

        /* online softmax */
        float mt0 = -1e30f, mt1 = -1e30f;
#pragma unroll
        for (int nt = 0; nt < 8; nt++) {
            mt0 = fmaxf(mt0, fmaxf(sc[nt][0], sc[nt][1]));
            mt1 = fmaxf(mt1, fmaxf(sc[nt][2], sc[nt][3]));
        }
        mt0 = fmaxf(mt0, __shfl_xor_sync(0xffffffffu, mt0, 1));
        mt0 = fmaxf(mt0, __shfl_xor_sync(0xffffffffu, mt0, 2));
        mt1 = fmaxf(mt1, __shfl_xor_sync(0xffffffffu, mt1, 1));
        mt1 = fmaxf(mt1, __shfl_xor_sync(0xffffffffu, mt1, 2));
        float mn0 = fmaxf(m0, mt0), mn1 = fmaxf(m1, mt1);
        float al0 = __expf(m0 - mn0), al1 = __expf(m1 - mn1);
        m0 = mn0; m1 = mn1;
        float s0 = 0.f, s1 = 0.f;
#pragma unroll
        for (int nt = 0; nt < 8; nt++) {
            sc[nt][0] = __expf(sc[nt][0] - mn0);
            sc[nt][1] = __expf(sc[nt][1] - mn0);
            sc[nt][2] = __expf(sc[nt][2] - mn1);
            sc[nt][3] = __expf(sc[nt][3] - mn1);
            s0 += sc[nt][0] + sc[nt][1];
            s1 += sc[nt][2] + sc[nt][3];
        }
        s0 += __shfl_xor_sync(0xffffffffu, s0, 1);
        s0 += __shfl_xor_sync(0xffffffffu, s0, 2);
        s1 += __shfl_xor_sync(0xffffffffu, s1, 1);
        s1 += __shfl_xor_sync(0xffffffffu, s1, 2);
        l0 = l0 * al0 + s0;
        l1 = l1 * al1 + s1;
#pragma unroll
        for (int nt = 0; nt < 16; nt++) {
            o[nt][0] *= al0; o[nt][1] *= al0;
            o[nt][2] *= al1; o[nt][3] *= al1;
        }

        /* O += P @ V */
        uint32_t bOffV = vB + ((g2 & 1) * 8 + (lane & 7)) * AROW + (g2 >> 1) * 16;
#pragma unroll
        for (int s = 0; s < 4; s++) {
            uint32_t ap[4];
            __half2 p0 = __floats2half2_rn(sc[2 * s][0],     sc[2 * s][1]);
            __half2 p1 = __floats2half2_rn(sc[2 * s][2],     sc[2 * s][3]);
            __half2 p2 = __floats2half2_rn(sc[2 * s + 1][0], sc[2 * s + 1][1]);
            __half2 p3 = __floats2half2_rn(sc[2 * s + 1][2], sc[2 * s + 1][3]);
            ap[0] = *(uint32_t*)&p0; ap[1] = *(uint32_t*)&p1;
            ap[2] = *(uint32_t*)&p2; ap[3] = *(uint32_t*)&p3;
#pragma unroll
            for (int p = 0; p < 8; p++) {
                uint32_t vb[4];
                ldm4t(vb, bOffV + s * (16 * AROW) + p * 32);
                mma_f16(o[2 * p],     ap, &vb[0]);
                mma_f16(o[2 * p + 1], ap, &vb[2]);
            }
        }
        __syncthreads();   /* protect stage reuse */
    }

    float inv0 = 1.f / l0, inv1 = 1.f / l1;
    int orow = q0 + wq * 16 + (lane >> 2);
    __half* ob0 = out + (size_t)orow * H + h * HD + 2 * (lane & 3);
    __half* ob1 = ob0 + 8 * H;
#pragma unroll
    for (int nt = 0; nt < 16; nt++) {
        __half2 v0 = __floats2half2_rn(o[nt][0] * inv0, o[nt][1] * inv0);
        __half2 v1 = __floats2half2_rn(o[nt][2] * inv1, o[nt][3] * inv1);
        *(__half2*)(ob0 + nt * 8) = v0;
        *(__half2*)(ob1 + nt * 8) = v1;
    }
}

/* ===================== fp16 tensor-core GEMM, direct fp32-W load =====================
 * C[M,N] = A[M,K] @ W[K,N].  A fp16 via cp.async (3 stages).
 * W fp32 LDG (2-chunk register prefetch) -> cvt fp16 -> STS (2 stages), ldmatrix.trans.
 * CTA 128x128, BK=64, 8 warps (4m x 2n). Optional fp16 output Ch. */
#define ROWA 144
#define ASTG (128 * ROWA)
#define NSA  3
#define ROWB2 272
#define BSTG (64 * ROWB2)
#define GSMEM (512 + NSA * ASTG + 2 * BSTG)

__global__ __launch_bounds__(256, 1) void mma_gemm_kernel(
    const uint4* __restrict__ A4, const float4* __restrict__ Wf,
    float* __restrict__ C, __half* __restrict__ Ch, const float* __restrict__ addC,
    int N, int K, int accumulate, int grouped)
{
    extern __shared__ __align__(16) char smem[];
    const int tid = threadIdx.x;
    const int wid = tid >> 5;
    const int lane = tid & 31;
    const int warp_m = wid >> 1;
    const int warp_n = wid & 1;
    const int n0 = blockIdx.x * 128;
    const int m0 = blockIdx.y * 128;
    const int N4 = N >> 2;

    if (grouped) {
        int cnt = g_cnt[blockIdx.z];
        if (m0 >= cnt) return;
        Wf += (size_t)blockIdx.z * K * N4;
    }
    int* rows = (int*)smem;
    {
        int cnt = grouped ? g_cnt[blockIdx.z] : 0;
        int off = grouped ? g_off[blockIdx.z] : 0;
        for (int i = tid; i < 128; i += 256)
            rows[i] = grouped ? ((m0 + i < cnt) ? g_perm[off + m0 + i] : -1) : (m0 + i);
    }
    __syncthreads();

    const uint32_t sb = smem_u32(smem);
    const uint32_t aBase = sb + 512;
    const uint32_t bBase = aBase + NSA * ASTG;
    const int K8 = K >> 3;
    const int nch = K >> 6;

    const int lrow = tid >> 1;
    const int cj = (tid & 1) * 4;
    int ra = rows[lrow];
    uint32_t szA = (ra >= 0) ? 16u : 0u;
    size_t ibA = (size_t)(ra >= 0 ? ra : 0) * K8 + cj;
    uint32_t dofA = (uint32_t)(lrow * ROWA + cj * 16);

    const int brow = tid >> 2;
    const int bq = tid & 3;
    const float4* wp0 = Wf + (size_t)brow * N4 + (n0 >> 2) + 2 * bq;
    const size_t wchunk = (size_t)64 * N4;
    uint32_t bsts = (uint32_t)(brow * ROWB2 + bq * 16);

    uint32_t aRowOff = (uint32_t)((warp_m * 32 + (lane & 15)) * ROWA + (lane >> 4) * 16);
    int g = lane >> 3;
    uint32_t bRowOff = (uint32_t)(((g & 1) * 8 + (lane & 7)) * ROWB2 +
                                  (warp_n * 64 + (g >> 1) * 8) * 2);

    float acc[2][8][4];
#pragma unroll
    for (int mt = 0; mt < 2; mt++)
#pragma unroll
        for (int nt = 0; nt < 8; nt++)
#pragma unroll
            for (int q = 0; q < 4; q++) acc[mt][nt][q] = 0.f;

    auto issueA = [&](int c) {
        uint32_t tb = aBase + (uint32_t)(c % NSA) * ASTG;
        size_t ko = (size_t)c * 8;
#pragma unroll
        for (int j2 = 0; j2 < 4; j2++)
            CP16(tb + dofA + j2 * 16, (const void*)(A4 + ibA + ko + j2), szA);
    };

    float4 br[2][8];
    auto ldgB = [&](int c, int b) {
        const float4* wp = wp0 + (size_t)c * wchunk;
#pragma unroll
        for (int j2 = 0; j2 < 4; j2++) {
            br[b][2 * j2]     = wp[8 * j2];
            br[b][2 * j2 + 1] = wp[8 * j2 + 1];
        }
    };
    auto stsB = [&](int s, int b) {
        uint32_t tb = bBase + (uint32_t)s * BSTG + bsts;
#pragma unroll
        for (int j2 = 0; j2 < 4; j2++) {
            uint4 pk = pack8h(br[b][2 * j2], br[b][2 * j2 + 1]);
            STS128(tb + j2 * 64, pk);
        }
    };

    /* prologue: B 2 chunks ahead, A 2 stages ahead */
    ldgB(0, 0);
    if (nch > 1) ldgB(1, 1);
    issueA(0);
    asm volatile("cp.async.commit_group;" ::: "memory");
    if (nch > 1) issueA(1);
    asm volatile("cp.async.commit_group;" ::: "memory");

    for (int c = 0; c < nch; c++) {
        stsB(c & 1, c & 1);
        asm volatile("cp.async.wait_group 1;" ::: "memory");
        __syncthreads();
        if (c + 2 < nch) issueA(c + 2);
        asm volatile("cp.async.commit_group;" ::: "memory");
        if (c + 2 < nch) ldgB(c + 2, c & 1);

        uint32_t aB = aBase + (uint32_t)(c % NSA) * ASTG;
        uint32_t bB = bBase + (uint32_t)(c & 1) * BSTG;
#pragma unroll
        for (int kk = 0; kk < 4; kk++) {
            uint32_t ah[2][4];
            ldm4(ah[0], aB + aRowOff + kk * 32);
            ldm4(ah[1], aB + aRowOff + 2304 + kk * 32);
            uint32_t bh[4][4];
#pragma unroll
            for (int p = 0; p < 4; p++)
                ldm4t(bh[p], bB + bRowOff + kk * (16 * ROWB2) + p * 32);
#pragma unroll
            for (int mt = 0; mt < 2; mt++)
#pragma unroll
                for (int p = 0; p < 4; p++)
#pragma unroll
                    for (int hh = 0; hh < 2; hh++)
                        mma_f16(acc[mt][p * 2 + hh], ah[mt], &bh[p][hh * 2]);
        }
    }

    /* epilogue */
    int lr = lane >> 2, lc = (lane & 3) * 2;
#pragma unroll
    for (int mt = 0; mt < 2; mt++) {
        int rloc = warp_m * 32 + mt * 16 + lr;
        int grow0 = rows[rloc];
        int grow1 = rows[rloc + 8];
#pragma unroll
        for (int nt = 0; nt < 8; nt++) {
            int col = n0 + warp_n * 64 + nt * 8 + lc;
            float* a4 = acc[mt][nt];
            if (Ch) {
                if (grow0 >= 0)
                    *(__half2*)(Ch + (size_t)grow0 * N + col) = __floats2half2_rn(a4[0], a4[1]);
                if (grow1 >= 0)
                    *(__half2*)(Ch + (size_t)grow1 * N + col) = __floats2half2_rn(a4[2], a4[3]);
            } else {
                if (grow0 >= 0) {
                    size_t cb = (size_t)grow0 * N + col;
                    if (accumulate) { C[cb] += a4[0]; C[cb + 1] += a4[1]; }
                    else if (addC)  { C[cb] = a4[0] + addC[cb]; C[cb + 1] = a4[1] + addC[cb + 1]; }
                    else            { C[cb] = a4[0]; C[cb + 1] = a4[1]; }
                }
                if (grow1 >= 0) {
                    size_t cb = (size_t)grow1 * N + col;
                    if (accumulate) { C[cb] += a4[2]; C[cb + 1] += a4[3]; }
                    else if (addC)  { C[cb] = a4[2] + addC[cb]; C[cb + 1] = a4[3] + addC[cb + 1]; }
                    else            { C[cb] = a4[2]; C[cb + 1] = a4[3]; }
                }
            }
        }
    }
}

/* ===================== router (fp16 xw out) ===================== */
__global__ void router_kernel(const float* __restrict__ x2, const float* __restrict__ rw,
                              int* __restrict__ topidx, __half* __restrict__ xwh)
{
    int t = blockIdx.x, tid = threadIdx.x;
    size_t base = (size_t)t * H;
    float part[E];
#pragma unroll
    for (int e = 0; e < E; e++) part[e] = 0.f;
    for (int c = tid; c < H; c += 256) {
        float xv = x2[base + c];
#pragma unroll
        for (int e = 0; e < E; e++) part[e] = fmaf(xv, rw[c * E + e], part[e]);
    }
    __shared__ float red[256][E];
#pragma unroll
    for (int e = 0; e < E; e++) red[tid][e] = part[e];
    __syncthreads();
    for (int s = 128; s > 0; s >>= 1) {
        if (tid < s)
#pragma unroll
            for (int e = 0; e < E; e++) red[tid][e] += red[tid + s][e];
        __syncthreads();
    }
    __shared__ float s_scale;
    if (tid == 0) {
        float best = red[0][0]; int bi = 0;
        for (int e = 1; e < E; e++) if (red[0][e] > best) { best = red[0][e]; bi = e; }
        topidx[t] = bi;
        s_scale = 1.f / (1.f + expf(-best));
    }
    __syncthreads();
    float scv = s_scale;
    for (int c = tid; c < H; c += 256) xwh[base + c] = __float2half(x2[base + c] * scv);
}

/* ===================== expert histogram + permutation ===================== */
__global__ void hist_kernel()
{
    __shared__ int cnt[E], off[E], run[E];
    int tid = threadIdx.x;
    if (tid < E) { cnt[tid] = 0; run[tid] = 0; }
    __syncthreads();
    for (int t = tid; t < T; t += 256) atomicAdd(&cnt[g_topidx[t]], 1);
    __syncthreads();
    if (tid == 0) {
        int o = 0;
        for (int e = 0; e < E; e++) { off[e] = o; o += cnt[e]; }
    }
    __syncthreads();
    for (int t = tid; t < T; t += 256) {
        int e = g_topidx[t];
        int p = atomicAdd(&run[e], 1);
        g_perm[off[e] + p] = t;
    }
    __syncthreads();
    if (tid < E) { g_cnt[tid] = cnt[tid]; g_off[tid] = off[tid]; }
}

/* ===================== silu(g)*u (fp16 in/out) ===================== */
__global__ void silu_cvt_kernel(const __half2* __restrict__ g, const __half2* __restrict__ u,
                                __half2* __restrict__ oh, int n2)
{
    int i = blockIdx.x * 256 + threadIdx.x;
    if (i < n2) {
        float2 gv = __half22float2(g[i]);
        float2 uv = __half22float2(u[i]);
        float r0 = gv.x / (1.f + __expf(-gv.x)) * uv.x;
        float r1 = gv.y / (1.f + __expf(-gv.y)) * uv.y;
        oh[i] = __floats2half2_rn(r0, r1);
    }
}

/* ===================== launch ===================== */
extern "C" void kernel_launch(void* const* d_in, const int* in_sizes, int n_in,
                              void* d_out, int out_size)
{
    (void)in_sizes; (void)n_in; (void)out_size;
    const int*   positions = (const int*)d_in[0];
    const float* hidden    = (const float*)d_in[1];
    const float* residual  = (const float*)d_in[2];
    const float* ln1w      = (const float*)d_in[3];
    const float* ln2w      = (const float*)d_in[4];
    const float* w_qkv     = (const float*)d_in[5];
    const float* w_o       = (const float*)d_in[6];
    const float* router_w  = (const float*)d_in[7];
    const float* we_gate   = (const float*)d_in[8];
    const float* we_up     = (const float*)d_in[9];
    const float* we_down   = (const float*)d_in[10];
    const float* ws_gate   = (const float*)d_in[11];
    const float* ws_up     = (const float*)d_in[12];
    const float* ws_down   = (const float*)d_in[13];

    float* out  = (float*)d_out;
    float* res2 = out + (size_t)T * H;

    float *p_res, *p_x, *p_qkv;
    int *p_top;
    uint4 *a1, *a2, *gh, *uh, *qh, *kh, *vh;
    cudaGetSymbolAddress((void**)&p_res,  g_res);
    cudaGetSymbolAddress((void**)&p_x,    g_x);
    cudaGetSymbolAddress((void**)&p_qkv,  g_qkv);
    cudaGetSymbolAddress((void**)&p_top,  g_topidx);
    cudaGetSymbolAddress((void**)&a1,  g_act1);
    cudaGetSymbolAddress((void**)&a2,  g_act2);
    cudaGetSymbolAddress((void**)&gh,  g_gh);
    cudaGetSymbolAddress((void**)&uh,  g_uh);
    cudaGetSymbolAddress((void**)&qh,  g_qh);
    cudaGetSymbolAddress((void**)&kh,  g_kh);
    cudaGetSymbolAddress((void**)&vh,  g_vh);
    __half* h1 = (__half*)a1;
    __half* h2 = (__half*)a2;

    cudaFuncSetAttribute(mma_gemm_kernel, cudaFuncAttributeMaxDynamicSharedMemorySize, GSMEM);
    cudaFuncSetAttribute(attn_mma_kernel, cudaFuncAttributeMaxDynamicSharedMemorySize, ASMEM);

    /* 1. hs = hidden+residual ; res ; xh = rmsnorm (fp16) */
    addnorm_kernel<<<T, 256>>>(hidden, residual, ln1w, p_res, 0, h1);
    /* 2. qkv = x @ w_qkv (fp32 out for rope) */
    mma_gemm_kernel<<<dim3(QKVW/128, T/128, 1), 256, GSMEM>>>(a1, (const float4*)w_qkv, p_qkv, 0, 0, QKVW, H, 0, 0);
    /* 3. rope + qknorm + fp16 conversion (q scaled) */
    rope_cvt_kernel<<<dim3(T, NH + 2*NKV), 128>>>(p_qkv, positions, (__half*)qh, (__half*)kh, (__half*)vh);
    /* 4. fp16 mma attention -> h1 */
    attn_mma_kernel<<<dim3(T/64, NH), 128, ASMEM>>>((const __half*)qh, (const __half*)kh, (const __half*)vh, h1);
    /* 5. res2 = attn @ w_o + res */
    mma_gemm_kernel<<<dim3(H/128, T/128, 1), 256, GSMEM>>>(a1, (const float4*)w_o, res2, 0, p_res, H, H, 0, 0);
    /* 6. x2 = rmsnorm(res2): fp32 for router + fp16 for GEMMs */
    addnorm_kernel<<<T, 256>>>(res2, 0, ln2w, 0, p_x, h1);
    /* 7-8. router + grouping */
    router_kernel<<<T, 256>>>(p_x, router_w, p_top, h2);
    hist_kernel<<<1, 256>>>();
    /* 9-12. shared expert (gate/up fp16 out) */
    mma_gemm_kernel<<<dim3(I_DIM/128, T/128, 1), 256, GSMEM>>>(a1, (const float4*)ws_gate, 0, (__half*)gh, 0, I_DIM, H, 0, 0);
    mma_gemm_kernel<<<dim3(I_DIM/128, T/128, 1), 256, GSMEM>>>(a1, (const float4*)ws_up,   0, (__half*)uh, 0, I_DIM, H, 0, 0);
    silu_cvt_kernel<<<((size_t)T*I_DIM/2 + 255)/256, 256>>>((const __half2*)gh, (const __half2*)uh, (__half2*)h1, T*I_DIM/2);
    mma_gemm_kernel<<<dim3(H/128, T/128, 1), 256, GSMEM>>>(a1, (const float4*)ws_down, out, 0, 0, H, I_DIM, 0, 0);
    /* 13-16. routed expert (top-1, grouped) */
    mma_gemm_kernel<<<dim3(I_DIM/128, T/128, E), 256, GSMEM>>>(a2, (const float4*)we_gate, 0, (__half*)gh, 0, I_DIM, H, 0, 1);
    mma_gemm_kernel<<<dim3(I_DIM/128, T/128, E), 256, GSMEM>>>(a2, (const float4*)we_up,   0, (__half*)uh, 0, I_DIM, H, 0, 1);
    silu_cvt_kernel<<<((size_t)T*I_DIM/2 + 255)/256, 256>>>((const __half2*)gh, (const __half2*)uh, (__half2*)h1, T*I_DIM/2);
    mma_gemm_kernel<<<dim3(H/128, T/128, E), 256, GSMEM>>>(a1, (const float4*)we_down, out, 0, 0, H, I_DIM, 1, 1);
}

// round 7
// speedup vs baseline: 8.9793x; 1.7743x over previous
#include <cuda_runtime.h>
#include <cuda_fp16.h>
#include <math.h>
#include <stdint.h>

#define T    2048
#define H    2048
#define NH   16
#define NKV  4
#define HD   128
#define E    8
#define I_DIM 4096
#define QKVW ((NH + 2*NKV) * HD)   /* 3072 */
#define EPSN 1e-5f
#define THETA_F 500000.0f
#define ATTN_SCALE 0.08838834764831845f

/* ===================== scratch (device globals) ===================== */
__device__ float g_res [T*H];
__device__ float g_x   [T*H];
__device__ float g_qkv [T*QKVW];
__device__ int   g_topidx[T];
__device__ int   g_perm[T];
__device__ int   g_cnt[E];
__device__ int   g_off[E];
/* fp16 buffers */
__device__ uint4 g_act1[(size_t)T*I_DIM/8];   /* x / attn-out / x2 / silu-out */
__device__ uint4 g_act2[(size_t)T*H/8];       /* xw */
__device__ uint4 g_gh[(size_t)T*I_DIM/8];     /* gate fp16 */
__device__ uint4 g_uh[(size_t)T*I_DIM/8];     /* up fp16 */
__device__ uint4 g_qh[(size_t)T*NH*HD/8];     /* q fp16 (scaled) [t][h][d] */
__device__ uint4 g_kh[(size_t)NKV*T*HD/8];    /* k fp16 [kvh][t][d] */
__device__ uint4 g_vh[(size_t)NKV*T*HD/8];    /* v fp16 [kvh][t][d] */

/* ===================== small PTX wrappers ===================== */
__device__ __forceinline__ uint32_t smem_u32(const void* p) {
    uint32_t a;
    asm("{ .reg .u64 t; cvta.to.shared.u64 t, %1; cvt.u32.u64 %0, t; }" : "=r"(a) : "l"(p));
    return a;
}
__device__ __forceinline__ void ldm4(uint32_t* r, uint32_t addr) {
    asm volatile("ldmatrix.sync.aligned.m8n8.x4.shared.b16 {%0,%1,%2,%3}, [%4];"
        : "=r"(r[0]), "=r"(r[1]), "=r"(r[2]), "=r"(r[3]) : "r"(addr));
}
__device__ __forceinline__ void ldm4t(uint32_t* r, uint32_t addr) {
    asm volatile("ldmatrix.sync.aligned.m8n8.x4.trans.shared.b16 {%0,%1,%2,%3}, [%4];"
        : "=r"(r[0]), "=r"(r[1]), "=r"(r[2]), "=r"(r[3]) : "r"(addr));
}
__device__ __forceinline__ void mma_f16(float* c, const uint32_t* a, const uint32_t* b) {
    asm volatile(
        "mma.sync.aligned.m16n8k16.row.col.f32.f16.f16.f32 "
        "{%0,%1,%2,%3}, {%4,%5,%6,%7}, {%8,%9}, {%0,%1,%2,%3};"
        : "+f"(c[0]), "+f"(c[1]), "+f"(c[2]), "+f"(c[3])
        : "r"(a[0]), "r"(a[1]), "r"(a[2]), "r"(a[3]), "r"(b[0]), "r"(b[1]));
}
#define CP16(dst, src, sz) asm volatile("cp.async.cg.shared.global [%0], [%1], 16, %2;" :: "r"(dst), "l"(src), "r"(sz) : "memory")
#define STS128(addr, v) asm volatile("st.shared.v4.b32 [%0], {%1,%2,%3,%4};" :: "r"(addr), "r"((v).x), "r"((v).y), "r"((v).z), "r"((v).w) : "memory")

__device__ __forceinline__ uint4 pack8h(float4 a, float4 b) {
    __half2 h0 = __floats2half2_rn(a.x, a.y);
    __half2 h1 = __floats2half2_rn(a.z, a.w);
    __half2 h2 = __floats2half2_rn(b.x, b.y);
    __half2 h3 = __floats2half2_rn(b.z, b.w);
    uint4 r;
    r.x = *(uint32_t*)&h0; r.y = *(uint32_t*)&h1;
    r.z = *(uint32_t*)&h2; r.w = *(uint32_t*)&h3;
    return r;
}

/* ===================== add + rmsnorm ===================== */
__global__ void addnorm_kernel(const float* __restrict__ a, const float* __restrict__ b,
                               const float* __restrict__ w, float* __restrict__ res,
                               float* __restrict__ xout, __half* __restrict__ xh)
{
    int t = blockIdx.x;
    int tid = threadIdx.x;
    const int PER = H / 256;
    size_t base = (size_t)t * H;
    float v[PER];
    float ss = 0.f;
#pragma unroll
    for (int u = 0; u < PER; u++) {
        int c = tid + u * 256;
        float val = a[base + c];
        if (b) val += b[base + c];
        v[u] = val;
        if (res) res[base + c] = val;
        ss += val * val;
    }
    __shared__ float red[256];
    red[tid] = ss;
    __syncthreads();
    for (int s = 128; s > 0; s >>= 1) {
        if (tid < s) red[tid] += red[tid + s];
        __syncthreads();
    }
    float scale = rsqrtf(red[0] / (float)H + EPSN);
#pragma unroll
    for (int u = 0; u < PER; u++) {
        int c = tid + u * 256;
        float o = v[u] * scale * w[c];
        if (xout) xout[base + c] = o;
        xh[base + c] = __float2half(o);
    }
}

/* ===================== rope + q/k rmsnorm + fp16 conversion ===================== */
__global__ void rope_cvt_kernel(const float* __restrict__ qkv, const int* __restrict__ positions,
                                __half* __restrict__ qh, __half* __restrict__ kh,
                                __half* __restrict__ vh)
{
    int t  = blockIdx.x;
    int hh = blockIdx.y;   /* 0..NH+2NKV-1 */
    int d  = threadIdx.x;
    const float* p = qkv + (size_t)t * QKVW + hh * HD;
    if (hh >= NH + NKV) {
        int kvh = hh - NH - NKV;
        vh[((size_t)kvh * T + t) * HD + d] = __float2half(p[d]);
        return;
    }
    float pos = (float)positions[t];
    int i = (d < 64) ? d : d - 64;
    float invf = powf(THETA_F, -(float)i / 64.f);
    float ang = pos * invf;
    float c = cosf(ang), s = sinf(ang);
    float x1 = p[i], x2 = p[i + 64];
    float val = (d < 64) ? (x1 * c - x2 * s) : (x2 * c + x1 * s);

    __shared__ float red[128];
    red[d] = val * val;
    __syncthreads();
    for (int st = 64; st > 0; st >>= 1) {
        if (d < st) red[d] += red[d + st];
        __syncthreads();
    }
    float scale = rsqrtf(red[0] / (float)HD + EPSN);
    val *= scale;
    if (hh < NH) qh[((size_t)t * NH + hh) * HD + d] = __float2half(val * ATTN_SCALE);
    else         kh[((size_t)(hh - NH) * T + t) * HD + d] = __float2half(val);
}

/* ===================== fp16 mma flash attention (causal, GQA) ===================== */
#define AROW 272
#define ATILE (64 * AROW)
#define ASMEM (5 * ATILE)

__global__ __launch_bounds__(128) void attn_mma_kernel(
    const __half* __restrict__ qh, const __half* __restrict__ kh,
    const __half* __restrict__ vh, __half* __restrict__ out)
{
    extern __shared__ __align__(16) char smem[];
    const int qb  = blockIdx.x;
    const int h   = blockIdx.y;
    const int kvh = h >> 2;
    const int tid = threadIdx.x;
    const int wq  = tid >> 5;
    const int lane = tid & 31;
    const int q0 = qb * 64;
    const int g2 = lane >> 3;

    uint32_t sb = smem_u32(smem);
    const uint32_t sK0 = sb + ATILE;
    const uint32_t sV0 = sb + 3 * ATILE;

    {
        const uint4* qg = (const uint4*)(qh + ((size_t)q0 * NH + h) * HD);
#pragma unroll
        for (int i = 0; i < 8; i++) {
            int idx = tid + i * 128;
            int row = idx >> 4, c = idx & 15;
            uint4 v = qg[(size_t)row * (NH * HD / 8) + c];
            *(uint4*)(smem + row * AROW + c * 16) = v;
        }
    }

    const char* kg = (const char*)(kh + (size_t)kvh * T * HD);
    const char* vg = (const char*)(vh + (size_t)kvh * T * HD);
    auto loadKV = [&](int kt, int s) {
        uint32_t dk = sK0 + (uint32_t)s * ATILE;
        uint32_t dv = sV0 + (uint32_t)s * ATILE;
        const char* kgt = kg + (size_t)kt * 64 * 256;
        const char* vgt = vg + (size_t)kt * 64 * 256;
#pragma unroll
        for (int i = 0; i < 8; i++) {
            int idx = tid + i * 128;
            int row = idx >> 4, c = idx & 15;
            uint32_t o = row * AROW + c * 16;
            int go = row * 256 + c * 16;
            CP16(dk + o, kgt + go, 16);
            CP16(dv + o, vgt + go, 16);
        }
    };

    loadKV(0, 0);
    asm volatile("cp.async.commit_group;" ::: "memory");
    __syncthreads();

    uint32_t aq[8][4];
    {
        uint32_t aOff = sb + (wq * 16 + (lane & 15)) * AROW + (lane >> 4) * 16;
#pragma unroll
        for (int kk = 0; kk < 8; kk++) ldm4(aq[kk], aOff + kk * 32);
    }

    float m0 = -1e30f, m1 = -1e30f, l0 = 0.f, l1 = 0.f;
    float o[16][4];
#pragma unroll
    for (int nt = 0; nt < 16; nt++)
#pragma unroll
        for (int q = 0; q < 4; q++) o[nt][q] = 0.f;

    const int ktmax = qb;
    for (int kt = 0; kt <= ktmax; kt++) {
        if (kt + 1 <= ktmax) loadKV(kt + 1, (kt + 1) & 1);
        asm volatile("cp.async.commit_group;" ::: "memory");
        if (kt == ktmax) asm volatile("cp.async.wait_group 0;" ::: "memory");
        else             asm volatile("cp.async.wait_group 1;" ::: "memory");
        __syncthreads();

        uint32_t kB = sK0 + (uint32_t)(kt & 1) * ATILE;
        uint32_t vB = sV0 + (uint32_t)(kt & 1) * ATILE;

        float sc[8][4];
#pragma unroll
        for (int nt = 0; nt < 8; nt++)
#pragma unroll
            for (int q = 0; q < 4; q++) sc[nt][q] = 0.f;

        uint32_t bOffK = kB + ((g2 >> 1) * 8 + (lane & 7)) * AROW + (g2 & 1) * 16;
#pragma unroll
        for (int kk = 0; kk < 8; kk++) {
            uint32_t kb[4][4];
#pragma unroll
            for (int p = 0; p < 4; p++)
                ldm4(kb[p], bOffK + p * (16 * AROW) + kk * 32);
#pragma unroll
            for (int p = 0; p < 4; p++) {
                mma_f16(sc[2 * p],     aq[kk], &kb[p][0]);
                mma_f16(sc[2 * p + 1], aq[kk], &kb[p][2]);
            }
        }

        int row0 = q0 + wq * 16 + (lane >> 2);
        if (kt == ktmax) {
            int colb = kt * 64 + 2 * (lane & 3);
#pragma unroll
            for (int nt = 0; nt < 8; nt++) {
                int c0 = colb + nt * 8;
                if (c0 > row0)         sc[nt][0] = -1e30f;
                if (c0 + 1 > row0)     sc[nt][1] = -1e30f;
                if (c0 > row0 + 8)     sc[nt][2] = -1e30f;
                if (c0 + 1 > row0 + 8) sc[nt][3] = -1e30f;
            }
        }

        float mt0 = -1e30f, mt1 = -1e30f;
#pragma unroll
        for (int nt = 0; nt < 8; nt++) {
            mt0 = fmaxf(mt0, fmaxf(sc[nt][0], sc[nt][1]));
            mt1 = fmaxf(mt1, fmaxf(sc[nt][2], sc[nt][3]));
        }
        mt0 = fmaxf(mt0, __shfl_xor_sync(0xffffffffu, mt0, 1));
        mt0 = fmaxf(mt0, __shfl_xor_sync(0xffffffffu, mt0, 2));
        mt1 = fmaxf(mt1, __shfl_xor_sync(0xffffffffu, mt1, 1));
        mt1 = fmaxf(mt1, __shfl_xor_sync(0xffffffffu, mt1, 2));
        float mn0 = fmaxf(m0, mt0), mn1 = fmaxf(m1, mt1);
        float al0 = __expf(m0 - mn0), al1 = __expf(m1 - mn1);
        m0 = mn0; m1 = mn1;
        float s0 = 0.f, s1 = 0.f;
#pragma unroll
        for (int nt = 0; nt < 8; nt++) {
            sc[nt][0] = __expf(sc[nt][0] - mn0);
            sc[nt][1] = __expf(sc[nt][1] - mn0);
            sc[nt][2] = __expf(sc[nt][2] - mn1);
            sc[nt][3] = __expf(sc[nt][3] - mn1);
            s0 += sc[nt][0] + sc[nt][1];
            s1 += sc[nt][2] + sc[nt][3];
        }
        s0 += __shfl_xor_sync(0xffffffffu, s0, 1);
        s0 += __shfl_xor_sync(0xffffffffu, s0, 2);
        s1 += __shfl_xor_sync(0xffffffffu, s1, 1);
        s1 += __shfl_xor_sync(0xffffffffu, s1, 2);
        l0 = l0 * al0 + s0;
        l1 = l1 * al1 + s1;
#pragma unroll
        for (int nt = 0; nt < 16; nt++) {
            o[nt][0] *= al0; o[nt][1] *= al0;
            o[nt][2] *= al1; o[nt][3] *= al1;
        }

        uint32_t bOffV = vB + ((g2 & 1) * 8 + (lane & 7)) * AROW + (g2 >> 1) * 16;
#pragma unroll
        for (int s = 0; s < 4; s++) {
            uint32_t ap[4];
            __half2 p0 = __floats2half2_rn(sc[2 * s][0],     sc[2 * s][1]);
            __half2 p1 = __floats2half2_rn(sc[2 * s][2],     sc[2 * s][3]);
            __half2 p2 = __floats2half2_rn(sc[2 * s + 1][0], sc[2 * s + 1][1]);
            __half2 p3 = __floats2half2_rn(sc[2 * s + 1][2], sc[2 * s + 1][3]);
            ap[0] = *(uint32_t*)&p0; ap[1] = *(uint32_t*)&p1;
            ap[2] = *(uint32_t*)&p2; ap[3] = *(uint32_t*)&p3;
#pragma unroll
            for (int p = 0; p < 8; p++) {
                uint32_t vb[4];
                ldm4t(vb, bOffV + s * (16 * AROW) + p * 32);
                mma_f16(o[2 * p],     ap, &vb[0]);
                mma_f16(o[2 * p + 1], ap, &vb[2]);
            }
        }
        __syncthreads();
    }

    float inv0 = 1.f / l0, inv1 = 1.f / l1;
    int orow = q0 + wq * 16 + (lane >> 2);
    __half* ob0 = out + (size_t)orow * H + h * HD + 2 * (lane & 3);
    __half* ob1 = ob0 + 8 * H;
#pragma unroll
    for (int nt = 0; nt < 16; nt++) {
        __half2 v0 = __floats2half2_rn(o[nt][0] * inv0, o[nt][1] * inv0);
        __half2 v1 = __floats2half2_rn(o[nt][2] * inv1, o[nt][3] * inv1);
        *(__half2*)(ob0 + nt * 8) = v0;
        *(__half2*)(ob1 + nt * 8) = v1;
    }
}

/* ===================== fp16 tensor-core GEMM, direct fp32-W load =====================
 * 2 CTAs/SM: single-buffer B register prefetch (LDG c+1 issued right after STS of c,
 * latency covered by chunk-c compute), __launch_bounds__(256,2). */
#define ROWA 144
#define ASTG (128 * ROWA)
#define NSA  3
#define ROWB2 272
#define BSTG (64 * ROWB2)
#define GSMEM (512 + NSA * ASTG + 2 * BSTG)

__global__ __launch_bounds__(256, 2) void mma_gemm_kernel(
    const uint4* __restrict__ A4, const float4* __restrict__ Wf,
    float* __restrict__ C, __half* __restrict__ Ch, const float* __restrict__ addC,
    int N, int K, int accumulate, int grouped)
{
    extern __shared__ __align__(16) char smem[];
    const int tid = threadIdx.x;
    const int wid = tid >> 5;
    const int lane = tid & 31;
    const int warp_m = wid >> 1;
    const int warp_n = wid & 1;
    const int n0 = blockIdx.x * 128;
    const int m0 = blockIdx.y * 128;
    const int N4 = N >> 2;

    if (grouped) {
        int cnt = g_cnt[blockIdx.z];
        if (m0 >= cnt) return;
        Wf += (size_t)blockIdx.z * K * N4;
    }
    int* rows = (int*)smem;
    {
        int cnt = grouped ? g_cnt[blockIdx.z] : 0;
        int off = grouped ? g_off[blockIdx.z] : 0;
        for (int i = tid; i < 128; i += 256)
            rows[i] = grouped ? ((m0 + i < cnt) ? g_perm[off + m0 + i] : -1) : (m0 + i);
    }
    __syncthreads();

    const uint32_t sb = smem_u32(smem);
    const uint32_t aBase = sb + 512;
    const uint32_t bBase = aBase + NSA * ASTG;
    const int K8 = K >> 3;
    const int nch = K >> 6;

    const int lrow = tid >> 1;
    const int cj = (tid & 1) * 4;
    int ra = rows[lrow];
    uint32_t szA = (ra >= 0) ? 16u : 0u;
    size_t ibA = (size_t)(ra >= 0 ? ra : 0) * K8 + cj;
    uint32_t dofA = (uint32_t)(lrow * ROWA + cj * 16);

    const int brow = tid >> 2;
    const int bq = tid & 3;
    const float4* wp0 = Wf + (size_t)brow * N4 + (n0 >> 2) + 2 * bq;
    const size_t wchunk = (size_t)64 * N4;
    uint32_t bsts = (uint32_t)(brow * ROWB2 + bq * 16);

    uint32_t aRowOff = (uint32_t)((warp_m * 32 + (lane & 15)) * ROWA + (lane >> 4) * 16);
    int g = lane >> 3;
    uint32_t bRowOff = (uint32_t)(((g & 1) * 8 + (lane & 7)) * ROWB2 +
                                  (warp_n * 64 + (g >> 1) * 8) * 2);

    float acc[2][8][4];
#pragma unroll
    for (int mt = 0; mt < 2; mt++)
#pragma unroll
        for (int nt = 0; nt < 8; nt++)
#pragma unroll
            for (int q = 0; q < 4; q++) acc[mt][nt][q] = 0.f;

    auto issueA = [&](int c) {
        uint32_t tb = aBase + (uint32_t)(c % NSA) * ASTG;
        size_t ko = (size_t)c * 8;
#pragma unroll
        for (int j2 = 0; j2 < 4; j2++)
            CP16(tb + dofA + j2 * 16, (const void*)(A4 + ibA + ko + j2), szA);
    };

    float4 br[8];   /* single-buffer weight prefetch */
    auto ldgB = [&](int c) {
        const float4* wp = wp0 + (size_t)c * wchunk;
#pragma unroll
        for (int j2 = 0; j2 < 4; j2++) {
            br[2 * j2]     = wp[8 * j2];
            br[2 * j2 + 1] = wp[8 * j2 + 1];
        }
    };
    auto stsB = [&](int s) {
        uint32_t tb = bBase + (uint32_t)s * BSTG + bsts;
#pragma unroll
        for (int j2 = 0; j2 < 4; j2++) {
            uint4 pk = pack8h(br[2 * j2], br[2 * j2 + 1]);
            STS128(tb + j2 * 64, pk);
        }
    };

    /* prologue */
    ldgB(0);
    issueA(0);
    asm volatile("cp.async.commit_group;" ::: "memory");
    if (nch > 1) issueA(1);
    asm volatile("cp.async.commit_group;" ::: "memory");

    for (int c = 0; c < nch; c++) {
        stsB(c & 1);
        if (c + 1 < nch) ldgB(c + 1);    /* latency covered by chunk-c compute */
        asm volatile("cp.async.wait_group 1;" ::: "memory");
        __syncthreads();
        if (c + 2 < nch) issueA(c + 2);
        asm volatile("cp.async.commit_group;" ::: "memory");

        uint32_t aB = aBase + (uint32_t)(c % NSA) * ASTG;
        uint32_t bB = bBase + (uint32_t)(c & 1) * BSTG;
#pragma unroll
        for (int kk = 0; kk < 4; kk++) {
            uint32_t ah[2][4];
            ldm4(ah[0], aB + aRowOff + kk * 32);
            ldm4(ah[1], aB + aRowOff + 2304 + kk * 32);
            uint32_t bh[4][4];
#pragma unroll
            for (int p = 0; p < 4; p++)
                ldm4t(bh[p], bB + bRowOff + kk * (16 * ROWB2) + p * 32);
#pragma unroll
            for (int mt = 0; mt < 2; mt++)
#pragma unroll
                for (int p = 0; p < 4; p++)
#pragma unroll
                    for (int hh = 0; hh < 2; hh++)
                        mma_f16(acc[mt][p * 2 + hh], ah[mt], &bh[p][hh * 2]);
        }
    }

    /* epilogue */
    int lr = lane >> 2, lc = (lane & 3) * 2;
#pragma unroll
    for (int mt = 0; mt < 2; mt++) {
        int rloc = warp_m * 32 + mt * 16 + lr;
        int grow0 = rows[rloc];
        int grow1 = rows[rloc + 8];
#pragma unroll
        for (int nt = 0; nt < 8; nt++) {
            int col = n0 + warp_n * 64 + nt * 8 + lc;
            float* a4 = acc[mt][nt];
            if (Ch) {
                if (grow0 >= 0)
                    *(__half2*)(Ch + (size_t)grow0 * N + col) = __floats2half2_rn(a4[0], a4[1]);
                if (grow1 >= 0)
                    *(__half2*)(Ch + (size_t)grow1 * N + col) = __floats2half2_rn(a4[2], a4[3]);
            } else {
                if (grow0 >= 0) {
                    size_t cb = (size_t)grow0 * N + col;
                    if (accumulate) { C[cb] += a4[0]; C[cb + 1] += a4[1]; }
                    else if (addC)  { C[cb] = a4[0] + addC[cb]; C[cb + 1] = a4[1] + addC[cb + 1]; }
                    else            { C[cb] = a4[0]; C[cb + 1] = a4[1]; }
                }
                if (grow1 >= 0) {
                    size_t cb = (size_t)grow1 * N + col;
                    if (accumulate) { C[cb] += a4[2]; C[cb + 1] += a4[3]; }
                    else if (addC)  { C[cb] = a4[2] + addC[cb]; C[cb + 1] = a4[3] + addC[cb + 1]; }
                    else            { C[cb] = a4[2]; C[cb + 1] = a4[3]; }
                }
            }
        }
    }
}

/* ===================== router (fp16 xw out) ===================== */
__global__ void router_kernel(const float* __restrict__ x2, const float* __restrict__ rw,
                              int* __restrict__ topidx, __half* __restrict__ xwh)
{
    int t = blockIdx.x, tid = threadIdx.x;
    size_t base = (size_t)t * H;
    float part[E];
#pragma unroll
    for (int e = 0; e < E; e++) part[e] = 0.f;
    for (int c = tid; c < H; c += 256) {
        float xv = x2[base + c];
#pragma unroll
        for (int e = 0; e < E; e++) part[e] = fmaf(xv, rw[c * E + e], part[e]);
    }
    __shared__ float red[256][E];
#pragma unroll
    for (int e = 0; e < E; e++) red[tid][e] = part[e];
    __syncthreads();
    for (int s = 128; s > 0; s >>= 1) {
        if (tid < s)
#pragma unroll
            for (int e = 0; e < E; e++) red[tid][e] += red[tid + s][e];
        __syncthreads();
    }
    __shared__ float s_scale;
    if (tid == 0) {
        float best = red[0][0]; int bi = 0;
        for (int e = 1; e < E; e++) if (red[0][e] > best) { best = red[0][e]; bi = e; }
        topidx[t] = bi;
        s_scale = 1.f / (1.f + expf(-best));
    }
    __syncthreads();
    float scv = s_scale;
    for (int c = tid; c < H; c += 256) xwh[base + c] = __float2half(x2[base + c] * scv);
}

/* ===================== expert histogram + permutation ===================== */
__global__ void hist_kernel()
{
    __shared__ int cnt[E], off[E], run[E];
    int tid = threadIdx.x;
    if (tid < E) { cnt[tid] = 0; run[tid] = 0; }
    __syncthreads();
    for (int t = tid; t < T; t += 256) atomicAdd(&cnt[g_topidx[t]], 1);
    __syncthreads();
    if (tid == 0) {
        int o = 0;
        for (int e = 0; e < E; e++) { off[e] = o; o += cnt[e]; }
    }
    __syncthreads();
    for (int t = tid; t < T; t += 256) {
        int e = g_topidx[t];
        int p = atomicAdd(&run[e], 1);
        g_perm[off[e] + p] = t;
    }
    __syncthreads();
    if (tid < E) { g_cnt[tid] = cnt[tid]; g_off[tid] = off[tid]; }
}

/* ===================== silu(g)*u (fp16 in/out) ===================== */
__global__ void silu_cvt_kernel(const __half2* __restrict__ g, const __half2* __restrict__ u,
                                __half2* __restrict__ oh, int n2)
{
    int i = blockIdx.x * 256 + threadIdx.x;
    if (i < n2) {
        float2 gv = __half22float2(g[i]);
        float2 uv = __half22float2(u[i]);
        float r0 = gv.x / (1.f + __expf(-gv.x)) * uv.x;
        float r1 = gv.y / (1.f + __expf(-gv.y)) * uv.y;
        oh[i] = __floats2half2_rn(r0, r1);
    }
}

/* ===================== launch ===================== */
extern "C" void kernel_launch(void* const* d_in, const int* in_sizes, int n_in,
                              void* d_out, int out_size)
{
    (void)in_sizes; (void)n_in; (void)out_size;
    const int*   positions = (const int*)d_in[0];
    const float* hidden    = (const float*)d_in[1];
    const float* residual  = (const float*)d_in[2];
    const float* ln1w      = (const float*)d_in[3];
    const float* ln2w      = (const float*)d_in[4];
    const float* w_qkv     = (const float*)d_in[5];
    const float* w_o       = (const float*)d_in[6];
    const float* router_w  = (const float*)d_in[7];
    const float* we_gate   = (const float*)d_in[8];
    const float* we_up     = (const float*)d_in[9];
    const float* we_down   = (const float*)d_in[10];
    const float* ws_gate   = (const float*)d_in[11];
    const float* ws_up     = (const float*)d_in[12];
    const float* ws_down   = (const float*)d_in[13];

    float* out  = (float*)d_out;
    float* res2 = out + (size_t)T * H;

    float *p_res, *p_x, *p_qkv;
    int *p_top;
    uint4 *a1, *a2, *gh, *uh, *qh, *kh, *vh;
    cudaGetSymbolAddress((void**)&p_res,  g_res);
    cudaGetSymbolAddress((void**)&p_x,    g_x);
    cudaGetSymbolAddress((void**)&p_qkv,  g_qkv);
    cudaGetSymbolAddress((void**)&p_top,  g_topidx);
    cudaGetSymbolAddress((void**)&a1,  g_act1);
    cudaGetSymbolAddress((void**)&a2,  g_act2);
    cudaGetSymbolAddress((void**)&gh,  g_gh);
    cudaGetSymbolAddress((void**)&uh,  g_uh);
    cudaGetSymbolAddress((void**)&qh,  g_qh);
    cudaGetSymbolAddress((void**)&kh,  g_kh);
    cudaGetSymbolAddress((void**)&vh,  g_vh);
    __half* h1 = (__half*)a1;
    __half* h2 = (__half*)a2;

    cudaFuncSetAttribute(mma_gemm_kernel, cudaFuncAttributeMaxDynamicSharedMemorySize, GSMEM);
    cudaFuncSetAttribute(attn_mma_kernel, cudaFuncAttributeMaxDynamicSharedMemorySize, ASMEM);

    /* 1. hs = hidden+residual ; res ; xh = rmsnorm (fp16) */
    addnorm_kernel<<<T, 256>>>(hidden, residual, ln1w, p_res, 0, h1);
    /* 2. qkv = x @ w_qkv (fp32 out for rope) */
    mma_gemm_kernel<<<dim3(QKVW/128, T/128, 1), 256, GSMEM>>>(a1, (const float4*)w_qkv, p_qkv, 0, 0, QKVW, H, 0, 0);
    /* 3. rope + qknorm + fp16 conversion (q scaled) */
    rope_cvt_kernel<<<dim3(T, NH + 2*NKV), 128>>>(p_qkv, positions, (__half*)qh, (__half*)kh, (__half*)vh);
    /* 4. fp16 mma attention -> h1 */
    attn_mma_kernel<<<dim3(T/64, NH), 128, ASMEM>>>((const __half*)qh, (const __half*)kh, (const __half*)vh, h1);
    /* 5. res2 = attn @ w_o + res */
    mma_gemm_kernel<<<dim3(H/128, T/128, 1), 256, GSMEM>>>(a1, (const float4*)w_o, res2, 0, p_res, H, H, 0, 0);
    /* 6. x2 = rmsnorm(res2): fp32 for router + fp16 for GEMMs */
    addnorm_kernel<<<T, 256>>>(res2, 0, ln2w, 0, p_x, h1);
    /* 7-8. router + grouping */
    router_kernel<<<T, 256>>>(p_x, router_w, p_top, h2);
    hist_kernel<<<1, 256>>>();
    /* 9-12. shared expert (gate/up fp16 out) */
    mma_gemm_kernel<<<dim3(I_DIM/128, T/128, 1), 256, GSMEM>>>(a1, (const float4*)ws_gate, 0, (__half*)gh, 0, I_DIM, H, 0, 0);
    mma_gemm_kernel<<<dim3(I_DIM/128, T/128, 1), 256, GSMEM>>>(a1, (const float4*)ws_up,   0, (__half*)uh, 0, I_DIM, H, 0, 0);
    silu_cvt_kernel<<<((size_t)T*I_DIM/2 + 255)/256, 256>>>((const __half2*)gh, (const __half2*)uh, (__half2*)h1, T*I_DIM/2);
    mma_gemm_kernel<<<dim3(H/128, T/128, 1), 256, GSMEM>>>(a1, (const float4*)ws_down, out, 0, 0, H, I_DIM, 0, 0);
    /* 13-16. routed expert (top-1, grouped) */
    mma_gemm_kernel<<<dim3(I_DIM/128, T/128, E), 256, GSMEM>>>(a2, (const float4*)we_gate, 0, (__half*)gh, 0, I_DIM, H, 0, 1);
    mma_gemm_kernel<<<dim3(I_DIM/128, T/128, E), 256, GSMEM>>>(a2, (const float4*)we_up,   0, (__half*)uh, 0, I_DIM, H, 0, 1);
    silu_cvt_kernel<<<((size_t)T*I_DIM/2 + 255)/256, 256>>>((const __half2*)gh, (const __half2*)uh, (__half2*)h1, T*I_DIM/2);
    mma_gemm_kernel<<<dim3(H/128, T/128, E), 256, GSMEM>>>(a1, (const float4*)we_down, out, 0, 0, H, I_DIM, 1, 1);
}